// round 3
// baseline (speedup 1.0000x reference)
#include <cuda_runtime.h>
#include <cuda_bf16.h>
#include <math.h>

// Problem constants
#define BB   32
#define NN   1024
#define CIN  64
#define CO   128
#define KNN  16
#define BNROWS (BB*NN)          // 32768
#define ROWS   (BNROWS*KNN)     // 524288
#define GEMM_BLOCKS (ROWS/128)  // 4096
#define EPSV 1e-5f

typedef unsigned long long ull;

// ------------------------- device scratch (static, no allocs) ----------------
static __device__ int   g_idx[ROWS];                  // 2 MB
static __device__ float g_center[BNROWS*CO];          // 16 MB
static __device__ float g_h[BNROWS*CO];               // 16 MB
static __device__ float g_sc[BNROWS*CO];              // 16 MB
static __device__ float g_x0[(size_t)ROWS*CO];        // 268 MB
static __device__ float g_x1[(size_t)ROWS*CO];        // 268 MB
static __device__ float g_part[GEMM_BLOCKS*256];      // 4 MB
static __device__ float g_partsc[256*256];            // 256 KB (shortcut stats)
static __device__ float g_coef[4*256];                // (a[128],d[128]) x4

// ------------------------- helpers -------------------------------------------
__device__ __forceinline__ void ffma2(ull& d, ull a, ull b) {
    asm("fma.rn.f32x2 %0, %1, %2, %0;" : "+l"(d) : "l"(a), "l"(b));
}
__device__ __forceinline__ ull dup2(float w) {
    ull r; asm("mov.b64 %0, {%1, %1};" : "=l"(r) : "f"(w)); return r;
}
__device__ __forceinline__ void unpack2(ull v, float& lo, float& hi) {
    asm("mov.b64 {%0, %1}, %2;" : "=f"(lo), "=f"(hi) : "l"(v));
}

// ------------------------- 1) kNN: warp per query ----------------------------
// 8 queries per 256-thread block; dist rows in smem; selection = 16 rounds of
// (32-elem scan per lane + 5-step shfl argmax). No __syncthreads in the loop.
__global__ __launch_bounds__(256)
void knn_kernel(const float* __restrict__ pts, int* __restrict__ idxout) {
    __shared__ float sx[NN], sy[NN], sz[NN], sxx[NN];   // 16 KB
    __shared__ float sdist[8][NN];                      // 32 KB
    int t = threadIdx.x;
    int wid = t >> 5, lane = t & 31;
    int blk = blockIdx.x;                 // 4096 blocks
    int b = blk >> 7;
    int n = ((blk & 127) << 3) + wid;     // query index within batch
    const float* P = pts + (size_t)b * 3 * NN;
    for (int m = t; m < NN; m += 256) {
        float x = P[m], y = P[NN + m], z = P[2*NN + m];
        sx[m] = x; sy[m] = y; sz[m] = z;
        sxx[m] = x*x + y*y + z*z;
    }
    __syncthreads();
    float qx = sx[n], qy = sy[n], qz = sz[n], qxx = sxx[n];
    float* dist = sdist[wid];
    int m0 = lane * 32;
    #pragma unroll
    for (int j = 0; j < 32; j++) {
        int m = m0 + j;
        float d = 2.f*(qx*sx[m] + qy*sy[m] + qz*sz[m]) - qxx - sxx[m];
        dist[m] = (m == n) ? -INFINITY : d;
    }
    __syncwarp();
    int* op = idxout + ((size_t)b*NN + n) * KNN;
    for (int r = 0; r < KNN; r++) {
        float bv = -INFINITY; int bi = 0;
        #pragma unroll
        for (int j = 0; j < 32; j++) {
            float d = dist[m0 + j];
            if (d > bv) { bv = d; bi = m0 + j; }   // ascending scan: smaller idx wins ties
        }
        #pragma unroll
        for (int s = 16; s > 0; s >>= 1) {
            float ov = __shfl_down_sync(0xffffffff, bv, s);
            int   oi = __shfl_down_sync(0xffffffff, bi, s);
            if (ov > bv || (ov == bv && oi < bi)) { bv = ov; bi = oi; }
        }
        bi = __shfl_sync(0xffffffff, bi, 0);
        if (lane == 0) op[r] = bi;
        if ((bi >> 5) == lane) dist[bi] = -INFINITY;
        __syncwarp();
    }
}

// ------------------------- 2) per-point GEMVs --------------------------------
__global__ void feat_kernel(const float* __restrict__ f,
                            const float* __restrict__ W0,
                            const float* __restrict__ Wsc,
                            float* __restrict__ center,
                            float* __restrict__ h,
                            float* __restrict__ sc) {
    __shared__ float fs[CIN][16];
    int base = blockIdx.x * 16;
    int b = base >> 10, n0 = base & 1023;
    int t = threadIdx.x;
    #pragma unroll
    for (int i = 0; i < 8; i++) {
        int idx = t + 128*i;
        int c = idx >> 4, j = idx & 15;
        fs[c][j] = f[(size_t)b*CIN*NN + c*NN + n0 + j];
    }
    __syncthreads();
    int o = t;
    float ctr[16], hh[16], ss[16];
    #pragma unroll
    for (int j = 0; j < 16; j++) { ctr[j]=0.f; hh[j]=0.f; ss[j]=0.f; }
    for (int c = 0; c < CIN; c++) {
        float w0a = W0[o*128 + c];
        float w0b = W0[o*128 + 64 + c];
        float ws  = Wsc[o*64 + c];
        float wc  = w0a - w0b;
        const float* fr = fs[c];
        #pragma unroll
        for (int j = 0; j < 16; j++) {
            float fv = fr[j];
            ctr[j] = fmaf(wc,  fv, ctr[j]);
            hh[j]  = fmaf(w0b, fv, hh[j]);
            ss[j]  = fmaf(ws,  fv, ss[j]);
        }
    }
    #pragma unroll
    for (int j = 0; j < 16; j++) {
        int row = base + j;
        center[row*CO + o] = ctr[j];
        h[row*CO + o]      = hh[j];
        sc[row*CO + o]     = ss[j];
    }
}

// ------------------------- 3) build layer-0 output + stats partials ----------
__global__ void build_kernel(const float* __restrict__ center,
                             const float* __restrict__ h,
                             const int* __restrict__ idx,
                             float* __restrict__ x0,
                             float* __restrict__ part) {
    __shared__ float red[8][132];
    int t = threadIdx.x;
    int oq = (t & 31) << 2;
    int strip = t >> 5;
    int bn = blockIdx.x * 8 + strip;
    int b = bn >> 10;
    float4 c4 = *reinterpret_cast<const float4*>(&center[bn*CO + oq]);
    const int* ip = idx + bn*KNN;
    float s0=0,s1=0,s2=0,s3=0, q0=0,q1=0,q2=0,q3=0;
    #pragma unroll
    for (int k = 0; k < KNN; k++) {
        int gi = ip[k];
        float4 h4 = *reinterpret_cast<const float4*>(&h[(b*NN + gi)*CO + oq]);
        float4 v;
        v.x = c4.x + h4.x; v.y = c4.y + h4.y; v.z = c4.z + h4.z; v.w = c4.w + h4.w;
        *reinterpret_cast<float4*>(&x0[(size_t)(bn*KNN + k)*CO + oq]) = v;
        s0 += v.x; s1 += v.y; s2 += v.z; s3 += v.w;
        q0 = fmaf(v.x,v.x,q0); q1 = fmaf(v.y,v.y,q1); q2 = fmaf(v.z,v.z,q2); q3 = fmaf(v.w,v.w,q3);
    }
    red[strip][oq+0]=s0; red[strip][oq+1]=s1; red[strip][oq+2]=s2; red[strip][oq+3]=s3;
    __syncthreads();
    if (t < 128) {
        float s = 0;
        #pragma unroll
        for (int q = 0; q < 8; q++) s += red[q][t];
        part[blockIdx.x*256 + t] = s;
    }
    __syncthreads();
    red[strip][oq+0]=q0; red[strip][oq+1]=q1; red[strip][oq+2]=q2; red[strip][oq+3]=q3;
    __syncthreads();
    if (t < 128) {
        float s = 0;
        #pragma unroll
        for (int q = 0; q < 8; q++) s += red[q][t];
        part[blockIdx.x*256 + 128 + t] = s;
    }
}

// ------------------------- 4) stats: partials -> (a, d) ----------------------
__global__ void stats_kernel(const float* __restrict__ part, int nparts,
                             const float* __restrict__ g, const float* __restrict__ bt,
                             float* __restrict__ coef, float invM) {
    __shared__ float ss[256], qq[256];
    int o = blockIdx.x, t = threadIdx.x;
    float s = 0.f, q = 0.f;
    for (int p = t; p < nparts; p += 256) {
        s += part[p*256 + o];
        q += part[p*256 + 128 + o];
    }
    ss[t] = s; qq[t] = q;
    __syncthreads();
    for (int st = 128; st > 0; st >>= 1) {
        if (t < st) { ss[t] += ss[t+st]; qq[t] += qq[t+st]; }
        __syncthreads();
    }
    if (t == 0) {
        float mean = ss[0] * invM;
        float var  = qq[0] * invM - mean*mean;
        float a = g[o] / sqrtf(var + EPSV);
        coef[o] = a;
        coef[128 + o] = bt[o] - mean * a;
    }
}

// coalesced partial-sum over sc (rows x 128), 128 rows per block
__global__ void colpart_kernel(const float* __restrict__ X, float* __restrict__ part) {
    __shared__ float sm0[2][128], sm1[2][128];
    int t = threadIdx.x;
    int o = t & 127, hf = t >> 7;
    int r0 = blockIdx.x * 128 + hf * 64;
    float s = 0.f, q = 0.f;
    for (int i = 0; i < 64; i++) {
        float v = X[(size_t)(r0 + i)*CO + o];
        s += v; q = fmaf(v, v, q);
    }
    sm0[hf][o] = s; sm1[hf][o] = q;
    __syncthreads();
    if (t < 128) {
        part[blockIdx.x*256 + t]       = sm0[0][t] + sm0[1][t];
        part[blockIdx.x*256 + 128 + t] = sm1[0][t] + sm1[1][t];
    }
}

// ------------------------- 5) fused act(prev BN)+GEMM + stats ----------------
__global__ __launch_bounds__(256, 2)
void gemm_kernel(const float* __restrict__ X, const float* __restrict__ W,
                 const float* __restrict__ coef, float* __restrict__ Y,
                 float* __restrict__ part) {
    __shared__ __align__(16) float As[16][132];
    __shared__ __align__(16) ull   Bs[16][128];
    __shared__ float sa[128], sd[128];
    __shared__ float red[16][128];
    int t = threadIdx.x;
    if (t < 128) { sa[t] = coef[t]; sd[t] = coef[128 + t]; }
    __syncthreads();
    int tx = t & 15, ty = t >> 4;
    int m0 = ty * 8, o0 = tx * 8;
    size_t mbase = (size_t)blockIdx.x * 128;

    ull acc[8][4];
    #pragma unroll
    for (int j = 0; j < 8; j++)
        #pragma unroll
        for (int ip = 0; ip < 4; ip++) acc[j][ip] = 0ULL;

    for (int kb = 0; kb < 8; kb++) {
        int cbase = kb * 16;
        #pragma unroll
        for (int i = 0; i < 8; i++) {
            int idx = t + 256*i;
            int c = idx & 15, m = idx >> 4;
            float x = X[(mbase + m)*CO + cbase + c];
            As[c][m] = fmaxf(fmaf(sa[cbase + c], x, sd[cbase + c]), 0.f);
        }
        #pragma unroll
        for (int i = 0; i < 8; i++) {
            int idx = t + 256*i;
            int c = idx & 15, o = idx >> 4;
            Bs[c][o] = dup2(W[o*CO + cbase + c]);
        }
        __syncthreads();
        #pragma unroll
        for (int k = 0; k < 16; k++) {
            ulonglong2 a01 = *reinterpret_cast<const ulonglong2*>(&As[k][m0]);
            ulonglong2 a23 = *reinterpret_cast<const ulonglong2*>(&As[k][m0 + 4]);
            ull av0 = a01.x, av1 = a01.y, av2 = a23.x, av3 = a23.y;
            const ulonglong2* bp = reinterpret_cast<const ulonglong2*>(&Bs[k][o0]);
            ulonglong2 b01 = bp[0], b23 = bp[1], b45 = bp[2], b67 = bp[3];
            ull bv[8] = {b01.x, b01.y, b23.x, b23.y, b45.x, b45.y, b67.x, b67.y};
            #pragma unroll
            for (int j = 0; j < 8; j++) {
                ffma2(acc[j][0], av0, bv[j]);
                ffma2(acc[j][1], av1, bv[j]);
                ffma2(acc[j][2], av2, bv[j]);
                ffma2(acc[j][3], av3, bv[j]);
            }
        }
        __syncthreads();
    }

    float ysum[8], ysq[8];
    #pragma unroll
    for (int j = 0; j < 8; j++) { ysum[j] = 0.f; ysq[j] = 0.f; }
    #pragma unroll
    for (int ip = 0; ip < 4; ip++) {
        float lo[8], hi[8];
        #pragma unroll
        for (int j = 0; j < 8; j++) unpack2(acc[j][ip], lo[j], hi[j]);
        size_t row = mbase + m0 + 2*ip;
        float4* d0 = reinterpret_cast<float4*>(&Y[row*CO + o0]);
        d0[0] = make_float4(lo[0], lo[1], lo[2], lo[3]);
        d0[1] = make_float4(lo[4], lo[5], lo[6], lo[7]);
        float4* d1 = reinterpret_cast<float4*>(&Y[(row + 1)*CO + o0]);
        d1[0] = make_float4(hi[0], hi[1], hi[2], hi[3]);
        d1[1] = make_float4(hi[4], hi[5], hi[6], hi[7]);
        #pragma unroll
        for (int j = 0; j < 8; j++) {
            ysum[j] += lo[j] + hi[j];
            ysq[j]  = fmaf(lo[j], lo[j], fmaf(hi[j], hi[j], ysq[j]));
        }
    }
    #pragma unroll
    for (int j = 0; j < 8; j++) red[ty][o0 + j] = ysum[j];
    __syncthreads();
    if (t < 128) {
        float s = 0;
        #pragma unroll
        for (int q = 0; q < 16; q++) s += red[q][t];
        part[blockIdx.x*256 + t] = s;
    }
    __syncthreads();
    #pragma unroll
    for (int j = 0; j < 8; j++) red[ty][o0 + j] = ysq[j];
    __syncthreads();
    if (t < 128) {
        float s = 0;
        #pragma unroll
        for (int q = 0; q < 16; q++) s += red[q][t];
        part[blockIdx.x*256 + 128 + t] = s;
    }
}

// ------------------------- 6) final: mean_k relu(bn2) + bn_sc + relu, transpose
// coalesced via padded smem tile: block = 32 n x 128 o
__global__ void final_kernel(const float* __restrict__ x2, const float* __restrict__ sc,
                             const float* __restrict__ coef2, const float* __restrict__ coefsc,
                             float* __restrict__ out) {
    __shared__ float tile[32*129];
    int t = threadIdx.x;
    int blk = blockIdx.x;               // 1024 = 32 b * 32 ngroups
    int b = blk >> 5;
    int n0 = (blk & 31) << 5;
    #pragma unroll
    for (int i = 0; i < 16; i++) {
        int idx = t + 256*i;
        int o = idx & 127, nn = idx >> 7;
        int bn = b*NN + n0 + nn;
        float a2 = coef2[o], d2 = coef2[128 + o];
        const float* xr = x2 + (size_t)bn * KNN * CO + o;
        float s = 0.f;
        #pragma unroll
        for (int k = 0; k < KNN; k++)
            s += fmaxf(fmaf(a2, xr[k*CO], d2), 0.f);
        float scv = sc[bn*CO + o];
        float as = coefsc[o], ds = coefsc[128 + o];
        tile[nn*129 + o] = fmaxf(fmaf(as, scv, ds) + s * (1.f/16.f), 0.f);
    }
    __syncthreads();
    #pragma unroll
    for (int i = 0; i < 16; i++) {
        int idx = t + 256*i;
        int nn = idx & 31, o = idx >> 5;
        out[(size_t)b*CO*NN + o*NN + n0 + nn] = tile[nn*129 + o];
    }
}

// ------------------------- host launcher -------------------------------------
extern "C" void kernel_launch(void* const* d_in, const int* in_sizes, int n_in,
                              void* d_out, int out_size) {
    const float* points   = (const float*)d_in[0];
    const float* features = (const float*)d_in[1];
    const float* W0  = (const float*)d_in[2];
    const float* g0  = (const float*)d_in[3];
    const float* b0  = (const float*)d_in[4];
    const float* W1  = (const float*)d_in[5];
    const float* g1  = (const float*)d_in[6];
    const float* b1  = (const float*)d_in[7];
    const float* W2  = (const float*)d_in[8];
    const float* g2  = (const float*)d_in[9];
    const float* b2  = (const float*)d_in[10];
    const float* Wsc = (const float*)d_in[11];
    const float* gsc = (const float*)d_in[12];
    const float* bsc = (const float*)d_in[13];
    float* out = (float*)d_out;

    void *p_idx, *p_center, *p_h, *p_sc, *p_x0, *p_x1, *p_part, *p_partsc, *p_coef;
    cudaGetSymbolAddress(&p_idx,    g_idx);
    cudaGetSymbolAddress(&p_center, g_center);
    cudaGetSymbolAddress(&p_h,      g_h);
    cudaGetSymbolAddress(&p_sc,     g_sc);
    cudaGetSymbolAddress(&p_x0,     g_x0);
    cudaGetSymbolAddress(&p_x1,     g_x1);
    cudaGetSymbolAddress(&p_part,   g_part);
    cudaGetSymbolAddress(&p_partsc, g_partsc);
    cudaGetSymbolAddress(&p_coef,   g_coef);

    int*   idx    = (int*)p_idx;
    float* center = (float*)p_center;
    float* h      = (float*)p_h;
    float* sc     = (float*)p_sc;
    float* x0     = (float*)p_x0;
    float* x1     = (float*)p_x1;
    float* part   = (float*)p_part;
    float* partsc = (float*)p_partsc;
    float* coef0  = (float*)p_coef;
    float* coef1  = coef0 + 256;
    float* coef2  = coef0 + 512;
    float* coef3  = coef0 + 768;

    const float invM  = 1.f / (float)ROWS;
    const float invMs = 1.f / (float)BNROWS;

    // Order chosen so launch index 5 (ncu -s 5 -c 1) is gemm_kernel.
    knn_kernel<<<GEMM_BLOCKS, 256>>>(points, idx);                      // 0
    feat_kernel<<<BNROWS/16, 128>>>(features, W0, Wsc, center, h, sc);  // 1
    build_kernel<<<GEMM_BLOCKS, 256>>>(center, h, idx, x0, part);       // 2
    stats_kernel<<<128, 256>>>(part, GEMM_BLOCKS, g0, b0, coef0, invM); // 3
    colpart_kernel<<<256, 256>>>(sc, partsc);                           // 4
    gemm_kernel<<<GEMM_BLOCKS, 256>>>(x0, W1, coef0, x1, part);         // 5  <-- profiled
    stats_kernel<<<128, 256>>>(part, GEMM_BLOCKS, g1, b1, coef1, invM); // 6
    gemm_kernel<<<GEMM_BLOCKS, 256>>>(x1, W2, coef1, x0, part);         // 7
    stats_kernel<<<128, 256>>>(part, GEMM_BLOCKS, g2, b2, coef2, invM); // 8
    stats_kernel<<<128, 256>>>(partsc, 256, gsc, bsc, coef3, invMs);    // 9
    final_kernel<<<1024, 256>>>(x0, sc, coef2, coef3, out);             // 10
}

// round 4
// speedup vs baseline: 1.2711x; 1.2711x over previous
#include <cuda_runtime.h>
#include <cuda_bf16.h>
#include <math.h>

// Problem constants
#define BB   32
#define NN   1024
#define CIN  64
#define CO   128
#define KNN  16
#define BNROWS (BB*NN)          // 32768
#define ROWS   (BNROWS*KNN)     // 524288
#define GEMM_BLOCKS (ROWS/128)  // 4096
#define EPSV 1e-5f

typedef unsigned long long ull;

// ------------------------- device scratch (static, no allocs) ----------------
static __device__ int   g_idx[ROWS];                  // 2 MB
static __device__ float g_center[BNROWS*CO];          // 16 MB
static __device__ float g_h[BNROWS*CO];               // 16 MB
static __device__ float g_sc[BNROWS*CO];              // 16 MB
static __device__ float g_x0[(size_t)ROWS*CO];        // 268 MB
static __device__ float g_x1[(size_t)ROWS*CO];        // 268 MB
static __device__ float g_part[GEMM_BLOCKS*256];      // 4 MB
static __device__ float g_partsc[256*256];            // 256 KB (shortcut stats)
static __device__ float g_coef[4*256];                // (a[128],d[128]) x4

// ------------------------- helpers -------------------------------------------
__device__ __forceinline__ void ffma2(ull& d, ull a, ull b) {
    asm("fma.rn.f32x2 %0, %1, %2, %0;" : "+l"(d) : "l"(a), "l"(b));
}
__device__ __forceinline__ ull dup2(float w) {
    ull r; asm("mov.b64 %0, {%1, %1};" : "=l"(r) : "f"(w)); return r;
}
__device__ __forceinline__ void unpack2(ull v, float& lo, float& hi) {
    asm("mov.b64 {%0, %1}, %2;" : "=f"(lo), "=f"(hi) : "l"(v));
}

// ------------------------- 1) kNN: warp per query, register-resident ---------
// 8 queries per 256-thread block (one per warp). Each lane holds 32 distances
// in REGISTERS (d[32], literal-indexed) + a 32-bit alive mask. A selection
// round = 32 predicated register compares + 5-step shfl argmax + 1 bit clear.
// Zero shared-memory traffic in the selection loop (R3's version had 32-way
// bank conflicts on every LDS there).
__global__ __launch_bounds__(256)
void knn_kernel(const float* __restrict__ pts, int* __restrict__ idxout) {
    __shared__ float sx[NN], sy[NN], sz[NN], sxx[NN];   // 16 KB
    int t = threadIdx.x;
    int wid = t >> 5, lane = t & 31;
    int blk = blockIdx.x;                 // 4096 blocks
    int b = blk >> 7;
    int n = ((blk & 127) << 3) + wid;     // query index within batch
    const float* P = pts + (size_t)b * 3 * NN;
    for (int m = t; m < NN; m += 256) {
        float x = P[m], y = P[NN + m], z = P[2*NN + m];
        sx[m] = x; sy[m] = y; sz[m] = z;
        sxx[m] = x*x + y*y + z*z;
    }
    __syncthreads();
    float qx = sx[n], qy = sy[n], qz = sz[n], qxx = sxx[n];
    // transposed fill: at step j, lanes read consecutive m -> conflict-free
    float d[32];
    #pragma unroll
    for (int j = 0; j < 32; j++) {
        int m = j*32 + lane;
        float dd = 2.f*(qx*sx[m] + qy*sy[m] + qz*sz[m]) - qxx - sxx[m];
        d[j] = (m == n) ? -INFINITY : dd;
    }
    int* op = idxout + ((size_t)b*NN + n) * KNN;
    unsigned alive = 0xffffffffu;
    for (int r = 0; r < KNN; r++) {
        float bv = -INFINITY; int bj = 0;
        #pragma unroll
        for (int j = 0; j < 32; j++) {
            float dj = (alive & (1u << j)) ? d[j] : -INFINITY;
            if (dj > bv) { bv = dj; bj = j; }   // ascending j: smallest m wins ties in-lane
        }
        int bi = bj*32 + lane;
        #pragma unroll
        for (int s = 16; s > 0; s >>= 1) {
            float ov = __shfl_down_sync(0xffffffffu, bv, s);
            int   oi = __shfl_down_sync(0xffffffffu, bi, s);
            if (ov > bv || (ov == bv && oi < bi)) { bv = ov; bi = oi; }
        }
        bi = __shfl_sync(0xffffffffu, bi, 0);
        if (lane == 0) op[r] = bi;
        if ((bi & 31) == lane) alive &= ~(1u << (bi >> 5));
    }
}

// ------------------------- 2) per-point GEMVs --------------------------------
__global__ void feat_kernel(const float* __restrict__ f,
                            const float* __restrict__ W0,
                            const float* __restrict__ Wsc,
                            float* __restrict__ center,
                            float* __restrict__ h,
                            float* __restrict__ sc) {
    __shared__ float fs[CIN][16];
    int base = blockIdx.x * 16;
    int b = base >> 10, n0 = base & 1023;
    int t = threadIdx.x;
    #pragma unroll
    for (int i = 0; i < 8; i++) {
        int idx = t + 128*i;
        int c = idx >> 4, j = idx & 15;
        fs[c][j] = f[(size_t)b*CIN*NN + c*NN + n0 + j];
    }
    __syncthreads();
    int o = t;
    float ctr[16], hh[16], ss[16];
    #pragma unroll
    for (int j = 0; j < 16; j++) { ctr[j]=0.f; hh[j]=0.f; ss[j]=0.f; }
    for (int c = 0; c < CIN; c++) {
        float w0a = W0[o*128 + c];
        float w0b = W0[o*128 + 64 + c];
        float ws  = Wsc[o*64 + c];
        float wc  = w0a - w0b;
        const float* fr = fs[c];
        #pragma unroll
        for (int j = 0; j < 16; j++) {
            float fv = fr[j];
            ctr[j] = fmaf(wc,  fv, ctr[j]);
            hh[j]  = fmaf(w0b, fv, hh[j]);
            ss[j]  = fmaf(ws,  fv, ss[j]);
        }
    }
    #pragma unroll
    for (int j = 0; j < 16; j++) {
        int row = base + j;
        center[row*CO + o] = ctr[j];
        h[row*CO + o]      = hh[j];
        sc[row*CO + o]     = ss[j];
    }
}

// ------------------------- 3) build layer-0 output + stats partials ----------
__global__ void build_kernel(const float* __restrict__ center,
                             const float* __restrict__ h,
                             const int* __restrict__ idx,
                             float* __restrict__ x0,
                             float* __restrict__ part) {
    __shared__ float red[8][132];
    int t = threadIdx.x;
    int oq = (t & 31) << 2;
    int strip = t >> 5;
    int bn = blockIdx.x * 8 + strip;
    int b = bn >> 10;
    float4 c4 = *reinterpret_cast<const float4*>(&center[bn*CO + oq]);
    const int* ip = idx + bn*KNN;
    float s0=0,s1=0,s2=0,s3=0, q0=0,q1=0,q2=0,q3=0;
    #pragma unroll
    for (int k = 0; k < KNN; k++) {
        int gi = ip[k];
        float4 h4 = *reinterpret_cast<const float4*>(&h[(b*NN + gi)*CO + oq]);
        float4 v;
        v.x = c4.x + h4.x; v.y = c4.y + h4.y; v.z = c4.z + h4.z; v.w = c4.w + h4.w;
        *reinterpret_cast<float4*>(&x0[(size_t)(bn*KNN + k)*CO + oq]) = v;
        s0 += v.x; s1 += v.y; s2 += v.z; s3 += v.w;
        q0 = fmaf(v.x,v.x,q0); q1 = fmaf(v.y,v.y,q1); q2 = fmaf(v.z,v.z,q2); q3 = fmaf(v.w,v.w,q3);
    }
    red[strip][oq+0]=s0; red[strip][oq+1]=s1; red[strip][oq+2]=s2; red[strip][oq+3]=s3;
    __syncthreads();
    if (t < 128) {
        float s = 0;
        #pragma unroll
        for (int q = 0; q < 8; q++) s += red[q][t];
        part[blockIdx.x*256 + t] = s;
    }
    __syncthreads();
    red[strip][oq+0]=q0; red[strip][oq+1]=q1; red[strip][oq+2]=q2; red[strip][oq+3]=q3;
    __syncthreads();
    if (t < 128) {
        float s = 0;
        #pragma unroll
        for (int q = 0; q < 8; q++) s += red[q][t];
        part[blockIdx.x*256 + 128 + t] = s;
    }
}

// ------------------------- 4) stats: partials -> (a, d) ----------------------
__global__ void stats_kernel(const float* __restrict__ part, int nparts,
                             const float* __restrict__ g, const float* __restrict__ bt,
                             float* __restrict__ coef, float invM) {
    __shared__ float ss[256], qq[256];
    int o = blockIdx.x, t = threadIdx.x;
    float s = 0.f, q = 0.f;
    for (int p = t; p < nparts; p += 256) {
        s += part[p*256 + o];
        q += part[p*256 + 128 + o];
    }
    ss[t] = s; qq[t] = q;
    __syncthreads();
    for (int st = 128; st > 0; st >>= 1) {
        if (t < st) { ss[t] += ss[t+st]; qq[t] += qq[t+st]; }
        __syncthreads();
    }
    if (t == 0) {
        float mean = ss[0] * invM;
        float var  = qq[0] * invM - mean*mean;
        float a = g[o] / sqrtf(var + EPSV);
        coef[o] = a;
        coef[128 + o] = bt[o] - mean * a;
    }
}

// coalesced partial-sum over sc (rows x 128), 128 rows per block
__global__ void colpart_kernel(const float* __restrict__ X, float* __restrict__ part) {
    __shared__ float sm0[2][128], sm1[2][128];
    int t = threadIdx.x;
    int o = t & 127, hf = t >> 7;
    int r0 = blockIdx.x * 128 + hf * 64;
    float s = 0.f, q = 0.f;
    for (int i = 0; i < 64; i++) {
        float v = X[(size_t)(r0 + i)*CO + o];
        s += v; q = fmaf(v, v, q);
    }
    sm0[hf][o] = s; sm1[hf][o] = q;
    __syncthreads();
    if (t < 128) {
        part[blockIdx.x*256 + t]       = sm0[0][t] + sm0[1][t];
        part[blockIdx.x*256 + 128 + t] = sm1[0][t] + sm1[1][t];
    }
}

// ------------------------- 5) fused act(prev BN)+GEMM + stats ----------------
__global__ __launch_bounds__(256, 2)
void gemm_kernel(const float* __restrict__ X, const float* __restrict__ W,
                 const float* __restrict__ coef, float* __restrict__ Y,
                 float* __restrict__ part) {
    __shared__ __align__(16) float As[16][132];
    __shared__ __align__(16) ull   Bs[16][128];
    __shared__ float sa[128], sd[128];
    __shared__ float red[16][128];
    int t = threadIdx.x;
    if (t < 128) { sa[t] = coef[t]; sd[t] = coef[128 + t]; }
    __syncthreads();
    int tx = t & 15, ty = t >> 4;
    int m0 = ty * 8, o0 = tx * 8;
    size_t mbase = (size_t)blockIdx.x * 128;

    ull acc[8][4];
    #pragma unroll
    for (int j = 0; j < 8; j++)
        #pragma unroll
        for (int ip = 0; ip < 4; ip++) acc[j][ip] = 0ULL;

    for (int kb = 0; kb < 8; kb++) {
        int cbase = kb * 16;
        #pragma unroll
        for (int i = 0; i < 8; i++) {
            int idx = t + 256*i;
            int c = idx & 15, m = idx >> 4;
            float x = X[(mbase + m)*CO + cbase + c];
            As[c][m] = fmaxf(fmaf(sa[cbase + c], x, sd[cbase + c]), 0.f);
        }
        #pragma unroll
        for (int i = 0; i < 8; i++) {
            int idx = t + 256*i;
            int c = idx & 15, o = idx >> 4;
            Bs[c][o] = dup2(W[o*CO + cbase + c]);
        }
        __syncthreads();
        #pragma unroll
        for (int k = 0; k < 16; k++) {
            ulonglong2 a01 = *reinterpret_cast<const ulonglong2*>(&As[k][m0]);
            ulonglong2 a23 = *reinterpret_cast<const ulonglong2*>(&As[k][m0 + 4]);
            ull av0 = a01.x, av1 = a01.y, av2 = a23.x, av3 = a23.y;
            const ulonglong2* bp = reinterpret_cast<const ulonglong2*>(&Bs[k][o0]);
            ulonglong2 b01 = bp[0], b23 = bp[1], b45 = bp[2], b67 = bp[3];
            ull bv[8] = {b01.x, b01.y, b23.x, b23.y, b45.x, b45.y, b67.x, b67.y};
            #pragma unroll
            for (int j = 0; j < 8; j++) {
                ffma2(acc[j][0], av0, bv[j]);
                ffma2(acc[j][1], av1, bv[j]);
                ffma2(acc[j][2], av2, bv[j]);
                ffma2(acc[j][3], av3, bv[j]);
            }
        }
        __syncthreads();
    }

    float ysum[8], ysq[8];
    #pragma unroll
    for (int j = 0; j < 8; j++) { ysum[j] = 0.f; ysq[j] = 0.f; }
    #pragma unroll
    for (int ip = 0; ip < 4; ip++) {
        float lo[8], hi[8];
        #pragma unroll
        for (int j = 0; j < 8; j++) unpack2(acc[j][ip], lo[j], hi[j]);
        size_t row = mbase + m0 + 2*ip;
        float4* d0 = reinterpret_cast<float4*>(&Y[row*CO + o0]);
        d0[0] = make_float4(lo[0], lo[1], lo[2], lo[3]);
        d0[1] = make_float4(lo[4], lo[5], lo[6], lo[7]);
        float4* d1 = reinterpret_cast<float4*>(&Y[(row + 1)*CO + o0]);
        d1[0] = make_float4(hi[0], hi[1], hi[2], hi[3]);
        d1[1] = make_float4(hi[4], hi[5], hi[6], hi[7]);
        #pragma unroll
        for (int j = 0; j < 8; j++) {
            ysum[j] += lo[j] + hi[j];
            ysq[j]  = fmaf(lo[j], lo[j], fmaf(hi[j], hi[j], ysq[j]));
        }
    }
    #pragma unroll
    for (int j = 0; j < 8; j++) red[ty][o0 + j] = ysum[j];
    __syncthreads();
    if (t < 128) {
        float s = 0;
        #pragma unroll
        for (int q = 0; q < 16; q++) s += red[q][t];
        part[blockIdx.x*256 + t] = s;
    }
    __syncthreads();
    #pragma unroll
    for (int j = 0; j < 8; j++) red[ty][o0 + j] = ysq[j];
    __syncthreads();
    if (t < 128) {
        float s = 0;
        #pragma unroll
        for (int q = 0; q < 16; q++) s += red[q][t];
        part[blockIdx.x*256 + 128 + t] = s;
    }
}

// ------------------------- 6) final: mean_k relu(bn2) + bn_sc + relu, transpose
__global__ void final_kernel(const float* __restrict__ x2, const float* __restrict__ sc,
                             const float* __restrict__ coef2, const float* __restrict__ coefsc,
                             float* __restrict__ out) {
    __shared__ float tile[32*129];
    int t = threadIdx.x;
    int blk = blockIdx.x;               // 1024 = 32 b * 32 ngroups
    int b = blk >> 5;
    int n0 = (blk & 31) << 5;
    #pragma unroll
    for (int i = 0; i < 16; i++) {
        int idx = t + 256*i;
        int o = idx & 127, nn = idx >> 7;
        int bn = b*NN + n0 + nn;
        float a2 = coef2[o], d2 = coef2[128 + o];
        const float* xr = x2 + (size_t)bn * KNN * CO + o;
        float s = 0.f;
        #pragma unroll
        for (int k = 0; k < KNN; k++)
            s += fmaxf(fmaf(a2, xr[k*CO], d2), 0.f);
        float scv = sc[bn*CO + o];
        float as = coefsc[o], ds = coefsc[128 + o];
        tile[nn*129 + o] = fmaxf(fmaf(as, scv, ds) + s * (1.f/16.f), 0.f);
    }
    __syncthreads();
    #pragma unroll
    for (int i = 0; i < 16; i++) {
        int idx = t + 256*i;
        int nn = idx & 31, o = idx >> 5;
        out[(size_t)b*CO*NN + o*NN + n0 + nn] = tile[nn*129 + o];
    }
}

// ------------------------- host launcher -------------------------------------
extern "C" void kernel_launch(void* const* d_in, const int* in_sizes, int n_in,
                              void* d_out, int out_size) {
    const float* points   = (const float*)d_in[0];
    const float* features = (const float*)d_in[1];
    const float* W0  = (const float*)d_in[2];
    const float* g0  = (const float*)d_in[3];
    const float* b0  = (const float*)d_in[4];
    const float* W1  = (const float*)d_in[5];
    const float* g1  = (const float*)d_in[6];
    const float* b1  = (const float*)d_in[7];
    const float* W2  = (const float*)d_in[8];
    const float* g2  = (const float*)d_in[9];
    const float* b2  = (const float*)d_in[10];
    const float* Wsc = (const float*)d_in[11];
    const float* gsc = (const float*)d_in[12];
    const float* bsc = (const float*)d_in[13];
    float* out = (float*)d_out;

    void *p_idx, *p_center, *p_h, *p_sc, *p_x0, *p_x1, *p_part, *p_partsc, *p_coef;
    cudaGetSymbolAddress(&p_idx,    g_idx);
    cudaGetSymbolAddress(&p_center, g_center);
    cudaGetSymbolAddress(&p_h,      g_h);
    cudaGetSymbolAddress(&p_sc,     g_sc);
    cudaGetSymbolAddress(&p_x0,     g_x0);
    cudaGetSymbolAddress(&p_x1,     g_x1);
    cudaGetSymbolAddress(&p_part,   g_part);
    cudaGetSymbolAddress(&p_partsc, g_partsc);
    cudaGetSymbolAddress(&p_coef,   g_coef);

    int*   idx    = (int*)p_idx;
    float* center = (float*)p_center;
    float* h      = (float*)p_h;
    float* sc     = (float*)p_sc;
    float* x0     = (float*)p_x0;
    float* x1     = (float*)p_x1;
    float* part   = (float*)p_part;
    float* partsc = (float*)p_partsc;
    float* coef0  = (float*)p_coef;
    float* coef1  = coef0 + 256;
    float* coef2  = coef0 + 512;
    float* coef3  = coef0 + 768;

    const float invM  = 1.f / (float)ROWS;
    const float invMs = 1.f / (float)BNROWS;

    // ncu samples process-launch #6 -> put the first gemm there.
    knn_kernel<<<GEMM_BLOCKS, 256>>>(points, idx);                      // 0
    feat_kernel<<<BNROWS/16, 128>>>(features, W0, Wsc, center, h, sc);  // 1
    build_kernel<<<GEMM_BLOCKS, 256>>>(center, h, idx, x0, part);       // 2
    colpart_kernel<<<256, 256>>>(sc, partsc);                           // 3
    stats_kernel<<<128, 256>>>(part, GEMM_BLOCKS, g0, b0, coef0, invM); // 4
    stats_kernel<<<128, 256>>>(partsc, 256, gsc, bsc, coef3, invMs);    // 5
    gemm_kernel<<<GEMM_BLOCKS, 256>>>(x0, W1, coef0, x1, part);         // 6  <-- profiled
    stats_kernel<<<128, 256>>>(part, GEMM_BLOCKS, g1, b1, coef1, invM); // 7
    gemm_kernel<<<GEMM_BLOCKS, 256>>>(x1, W2, coef1, x0, part);         // 8
    stats_kernel<<<128, 256>>>(part, GEMM_BLOCKS, g2, b2, coef2, invM); // 9
    final_kernel<<<1024, 256>>>(x0, sc, coef2, coef3, out);             // 10
}

// round 5
// speedup vs baseline: 2.5501x; 2.0063x over previous
#include <cuda_runtime.h>
#include <cuda_bf16.h>
#include <math.h>

// Problem constants
#define BB   32
#define NN   1024
#define CIN  64
#define CO   128
#define KNN  16
#define BNROWS (BB*NN)          // 32768
#define ROWS   (BNROWS*KNN)     // 524288
#define GEMM_BLOCKS (ROWS/128)  // 4096
#define EPSV 1e-5f

typedef unsigned long long ull;

// ------------------------- device scratch (static, no allocs) ----------------
static __device__ int   g_idx[ROWS];                  // 2 MB
static __device__ float g_center[BNROWS*CO];          // 16 MB
static __device__ float g_h[BNROWS*CO];               // 16 MB
static __device__ float g_sc[BNROWS*CO];              // 16 MB
static __device__ float g_x1[(size_t)ROWS*CO];        // 268 MB (layer-1 out)
static __device__ float g_x2[(size_t)ROWS*CO];        // 268 MB (layer-2 out)
static __device__ float g_part[GEMM_BLOCKS*256];      // 4 MB
static __device__ float g_partsc[256*256];            // 256 KB
static __device__ float g_coef[4*256];                // (a[128],d[128]) x4

// ------------------------- helpers -------------------------------------------
__device__ __forceinline__ void ffma2(ull& d, ull a, ull b) {
    asm("fma.rn.f32x2 %0, %1, %2, %0;" : "+l"(d) : "l"(a), "l"(b));
}
__device__ __forceinline__ ull dup2(float w) {
    ull r; asm("mov.b64 %0, {%1, %1};" : "=l"(r) : "f"(w)); return r;
}
__device__ __forceinline__ void unpack2(ull v, float& lo, float& hi) {
    asm("mov.b64 {%0, %1}, %2;" : "=f"(lo), "=f"(hi) : "l"(v));
}

// ------------------------- 1) kNN: warp per query, register-resident ---------
__global__ __launch_bounds__(256)
void knn_kernel(const float* __restrict__ pts, int* __restrict__ idxout) {
    __shared__ float sx[NN], sy[NN], sz[NN], sxx[NN];
    int t = threadIdx.x;
    int wid = t >> 5, lane = t & 31;
    int blk = blockIdx.x;
    int b = blk >> 7;
    int n = ((blk & 127) << 3) + wid;
    const float* P = pts + (size_t)b * 3 * NN;
    for (int m = t; m < NN; m += 256) {
        float x = P[m], y = P[NN + m], z = P[2*NN + m];
        sx[m] = x; sy[m] = y; sz[m] = z;
        sxx[m] = x*x + y*y + z*z;
    }
    __syncthreads();
    float qx = sx[n], qy = sy[n], qz = sz[n], qxx = sxx[n];
    float d[32];
    #pragma unroll
    for (int j = 0; j < 32; j++) {
        int m = j*32 + lane;
        float dd = 2.f*(qx*sx[m] + qy*sy[m] + qz*sz[m]) - qxx - sxx[m];
        d[j] = (m == n) ? -INFINITY : dd;
    }
    int* op = idxout + ((size_t)b*NN + n) * KNN;
    unsigned alive = 0xffffffffu;
    for (int r = 0; r < KNN; r++) {
        float bv = -INFINITY; int bj = 0;
        #pragma unroll
        for (int j = 0; j < 32; j++) {
            float dj = (alive & (1u << j)) ? d[j] : -INFINITY;
            if (dj > bv) { bv = dj; bj = j; }
        }
        int bi = bj*32 + lane;
        #pragma unroll
        for (int s = 16; s > 0; s >>= 1) {
            float ov = __shfl_down_sync(0xffffffffu, bv, s);
            int   oi = __shfl_down_sync(0xffffffffu, bi, s);
            if (ov > bv || (ov == bv && oi < bi)) { bv = ov; bi = oi; }
        }
        bi = __shfl_sync(0xffffffffu, bi, 0);
        if (lane == 0) op[r] = bi;
        if ((bi & 31) == lane) alive &= ~(1u << (bi >> 5));
    }
}

// ------------------------- 2) per-point GEMVs --------------------------------
__global__ void feat_kernel(const float* __restrict__ f,
                            const float* __restrict__ W0,
                            const float* __restrict__ Wsc,
                            float* __restrict__ center,
                            float* __restrict__ h,
                            float* __restrict__ sc) {
    __shared__ float fs[CIN][16];
    int base = blockIdx.x * 16;
    int b = base >> 10, n0 = base & 1023;
    int t = threadIdx.x;
    #pragma unroll
    for (int i = 0; i < 8; i++) {
        int idx = t + 128*i;
        int c = idx >> 4, j = idx & 15;
        fs[c][j] = f[(size_t)b*CIN*NN + c*NN + n0 + j];
    }
    __syncthreads();
    int o = t;
    float ctr[16], hh[16], ss[16];
    #pragma unroll
    for (int j = 0; j < 16; j++) { ctr[j]=0.f; hh[j]=0.f; ss[j]=0.f; }
    for (int c = 0; c < CIN; c++) {
        float w0a = W0[o*128 + c];
        float w0b = W0[o*128 + 64 + c];
        float ws  = Wsc[o*64 + c];
        float wc  = w0a - w0b;
        const float* fr = fs[c];
        #pragma unroll
        for (int j = 0; j < 16; j++) {
            float fv = fr[j];
            ctr[j] = fmaf(wc,  fv, ctr[j]);
            hh[j]  = fmaf(w0b, fv, hh[j]);
            ss[j]  = fmaf(ws,  fv, ss[j]);
        }
    }
    #pragma unroll
    for (int j = 0; j < 16; j++) {
        int row = base + j;
        center[row*CO + o] = ctr[j];
        h[row*CO + o]      = hh[j];
        sc[row*CO + o]     = ss[j];
    }
}

// ------------------------- 3) layer-0 stats only (x0 never materialized) -----
__global__ void buildstats_kernel(const float* __restrict__ center,
                                  const float* __restrict__ h,
                                  const int* __restrict__ idx,
                                  float* __restrict__ part) {
    __shared__ float red[8][132];
    int t = threadIdx.x;
    int oq = (t & 31) << 2;
    int strip = t >> 5;
    int bn = blockIdx.x * 8 + strip;
    int b = bn >> 10;
    float4 c4 = *reinterpret_cast<const float4*>(&center[bn*CO + oq]);
    const int* ip = idx + bn*KNN;
    float s0=0,s1=0,s2=0,s3=0, q0=0,q1=0,q2=0,q3=0;
    #pragma unroll
    for (int k = 0; k < KNN; k++) {
        int gi = ip[k];
        float4 h4 = *reinterpret_cast<const float4*>(&h[(b*NN + gi)*CO + oq]);
        float vx = c4.x + h4.x, vy = c4.y + h4.y, vz = c4.z + h4.z, vw = c4.w + h4.w;
        s0 += vx; s1 += vy; s2 += vz; s3 += vw;
        q0 = fmaf(vx,vx,q0); q1 = fmaf(vy,vy,q1); q2 = fmaf(vz,vz,q2); q3 = fmaf(vw,vw,q3);
    }
    red[strip][oq+0]=s0; red[strip][oq+1]=s1; red[strip][oq+2]=s2; red[strip][oq+3]=s3;
    __syncthreads();
    if (t < 128) {
        float s = 0;
        #pragma unroll
        for (int q = 0; q < 8; q++) s += red[q][t];
        part[blockIdx.x*256 + t] = s;
    }
    __syncthreads();
    red[strip][oq+0]=q0; red[strip][oq+1]=q1; red[strip][oq+2]=q2; red[strip][oq+3]=q3;
    __syncthreads();
    if (t < 128) {
        float s = 0;
        #pragma unroll
        for (int q = 0; q < 8; q++) s += red[q][t];
        part[blockIdx.x*256 + 128 + t] = s;
    }
}

// ------------------------- 4) stats: partials -> (a, d) ----------------------
__global__ void stats_kernel(const float* __restrict__ part, int nparts,
                             const float* __restrict__ g, const float* __restrict__ bt,
                             float* __restrict__ coef, float invM) {
    __shared__ float ss[256], qq[256];
    int o = blockIdx.x, t = threadIdx.x;
    float s = 0.f, q = 0.f;
    for (int p = t; p < nparts; p += 256) {
        s += part[p*256 + o];
        q += part[p*256 + 128 + o];
    }
    ss[t] = s; qq[t] = q;
    __syncthreads();
    for (int st = 128; st > 0; st >>= 1) {
        if (t < st) { ss[t] += ss[t+st]; qq[t] += qq[t+st]; }
        __syncthreads();
    }
    if (t == 0) {
        float mean = ss[0] * invM;
        float var  = qq[0] * invM - mean*mean;
        float a = g[o] / sqrtf(var + EPSV);
        coef[o] = a;
        coef[128 + o] = bt[o] - mean * a;
    }
}

// coalesced partial-sum over sc (rows x 128), 128 rows per block
__global__ void colpart_kernel(const float* __restrict__ X, float* __restrict__ part) {
    __shared__ float sm0[2][128], sm1[2][128];
    int t = threadIdx.x;
    int o = t & 127, hf = t >> 7;
    int r0 = blockIdx.x * 128 + hf * 64;
    float s = 0.f, q = 0.f;
    for (int i = 0; i < 64; i++) {
        float v = X[(size_t)(r0 + i)*CO + o];
        s += v; q = fmaf(v, v, q);
    }
    sm0[hf][o] = s; sm1[hf][o] = q;
    __syncthreads();
    if (t < 128) {
        part[blockIdx.x*256 + t]       = sm0[0][t] + sm0[1][t];
        part[blockIdx.x*256 + 128 + t] = sm1[0][t] + sm1[1][t];
    }
}

// ------------------------- GEMM core (shared by both layers) -----------------
// 256 threads, tile 128m x 128o, K=128 in 8 steps of 16.
// acc packed over o-pairs: acc[m][p] = (o0+2p, o0+2p+1). Low register pressure:
// per k only bv[4] + one transient dup. B stored natural (no duplication).
struct GemmSmem {
    float As[16][132];
    float Bs[16][132];
    float sa[128], sd[128];
    float red[16][128];
    int   offC[128];
    int   offH[128];
};

__device__ __forceinline__ void gemm_core(GemmSmem& S, int t,
                                          const float* __restrict__ X,     // may be null (fused)
                                          const float* __restrict__ center,
                                          const float* __restrict__ h,
                                          const float* __restrict__ W,
                                          float* __restrict__ Y,
                                          float* __restrict__ part,
                                          size_t mbase, int blockId, bool fused) {
    int tx = t & 15, ty = t >> 4;
    int m0 = ty * 8, o0 = tx * 8;

    ull acc[8][4];
    #pragma unroll
    for (int m = 0; m < 8; m++)
        #pragma unroll
        for (int p = 0; p < 4; p++) acc[m][p] = 0ULL;

    for (int kb = 0; kb < 8; kb++) {
        int cbase = kb * 16;
        if (fused) {
            #pragma unroll
            for (int i = 0; i < 8; i++) {
                int idxl = t + 256*i;
                int c = idxl & 15, m = idxl >> 4;
                float v = center[S.offC[m] + cbase + c] + h[S.offH[m] + cbase + c];
                S.As[c][m] = fmaxf(fmaf(S.sa[cbase + c], v, S.sd[cbase + c]), 0.f);
            }
        } else {
            #pragma unroll
            for (int i = 0; i < 8; i++) {
                int idxl = t + 256*i;
                int c = idxl & 15, m = idxl >> 4;
                float x = X[(mbase + m)*CO + cbase + c];
                S.As[c][m] = fmaxf(fmaf(S.sa[cbase + c], x, S.sd[cbase + c]), 0.f);
            }
        }
        #pragma unroll
        for (int i = 0; i < 8; i++) {
            int idxl = t + 256*i;
            int c = idxl & 15, o = idxl >> 4;
            S.Bs[c][o] = W[o*CO + cbase + c];
        }
        __syncthreads();
        #pragma unroll
        for (int k = 0; k < 16; k++) {
            ulonglong2 b01 = *reinterpret_cast<const ulonglong2*>(&S.Bs[k][o0]);
            ulonglong2 b23 = *reinterpret_cast<const ulonglong2*>(&S.Bs[k][o0 + 4]);
            ull bv0 = b01.x, bv1 = b01.y, bv2 = b23.x, bv3 = b23.y;
            float4 a0 = *reinterpret_cast<const float4*>(&S.As[k][m0]);
            float4 a1 = *reinterpret_cast<const float4*>(&S.As[k][m0 + 4]);
            float am[8] = {a0.x,a0.y,a0.z,a0.w,a1.x,a1.y,a1.z,a1.w};
            #pragma unroll
            for (int m = 0; m < 8; m++) {
                ull ad = dup2(am[m]);
                ffma2(acc[m][0], ad, bv0);
                ffma2(acc[m][1], ad, bv1);
                ffma2(acc[m][2], ad, bv2);
                ffma2(acc[m][3], ad, bv3);
            }
        }
        __syncthreads();
    }

    // epilogue: store + channel partials
    float ysum[8], ysq[8];
    #pragma unroll
    for (int j = 0; j < 8; j++) { ysum[j] = 0.f; ysq[j] = 0.f; }
    #pragma unroll
    for (int m = 0; m < 8; m++) {
        float v[8];
        #pragma unroll
        for (int p = 0; p < 4; p++) unpack2(acc[m][p], v[2*p], v[2*p+1]);
        size_t row = mbase + m0 + m;
        float4* dp = reinterpret_cast<float4*>(&Y[row*CO + o0]);
        dp[0] = make_float4(v[0], v[1], v[2], v[3]);
        dp[1] = make_float4(v[4], v[5], v[6], v[7]);
        #pragma unroll
        for (int j = 0; j < 8; j++) {
            ysum[j] += v[j];
            ysq[j]  = fmaf(v[j], v[j], ysq[j]);
        }
    }
    #pragma unroll
    for (int j = 0; j < 8; j++) S.red[ty][o0 + j] = ysum[j];
    __syncthreads();
    if (t < 128) {
        float s = 0;
        #pragma unroll
        for (int q = 0; q < 16; q++) s += S.red[q][t];
        part[blockId*256 + t] = s;
    }
    __syncthreads();
    #pragma unroll
    for (int j = 0; j < 8; j++) S.red[ty][o0 + j] = ysq[j];
    __syncthreads();
    if (t < 128) {
        float s = 0;
        #pragma unroll
        for (int q = 0; q < 16; q++) s += S.red[q][t];
        part[blockId*256 + 128 + t] = s;
    }
}

// layer 1: fused edge-build (A generated from center + gathered h)
__global__ __launch_bounds__(256, 2)
void gemm1_kernel(const float* __restrict__ center, const float* __restrict__ h,
                  const int* __restrict__ idx, const float* __restrict__ W,
                  const float* __restrict__ coef, float* __restrict__ Y,
                  float* __restrict__ part) {
    __shared__ GemmSmem S;
    int t = threadIdx.x;
    size_t mbase = (size_t)blockIdx.x * 128;
    if (t < 128) { S.sa[t] = coef[t]; S.sd[t] = coef[128 + t]; }
    if (t < 128) {
        int m = (int)mbase + t;
        int bn = m >> 4;
        int gi = idx[m];                 // idx is [bn][k] contiguous
        S.offC[t] = bn * CO;
        S.offH[t] = ((bn >> 10) * NN + gi) * CO;
    }
    __syncthreads();
    gemm_core(S, t, nullptr, center, h, W, Y, part, mbase, blockIdx.x, true);
}

// layer 2: plain (reads x1)
__global__ __launch_bounds__(256, 2)
void gemm2_kernel(const float* __restrict__ X, const float* __restrict__ W,
                  const float* __restrict__ coef, float* __restrict__ Y,
                  float* __restrict__ part) {
    __shared__ GemmSmem S;
    int t = threadIdx.x;
    size_t mbase = (size_t)blockIdx.x * 128;
    if (t < 128) { S.sa[t] = coef[t]; S.sd[t] = coef[128 + t]; }
    __syncthreads();
    gemm_core(S, t, X, nullptr, nullptr, W, Y, part, mbase, blockIdx.x, false);
}

// ------------------------- 6) final: mean_k relu(bn2) + bn_sc + relu, transpose
__global__ void final_kernel(const float* __restrict__ x2, const float* __restrict__ sc,
                             const float* __restrict__ coef2, const float* __restrict__ coefsc,
                             float* __restrict__ out) {
    __shared__ float tile[32*129];
    int t = threadIdx.x;
    int blk = blockIdx.x;
    int b = blk >> 5;
    int n0 = (blk & 31) << 5;
    #pragma unroll
    for (int i = 0; i < 16; i++) {
        int idx = t + 256*i;
        int o = idx & 127, nn = idx >> 7;
        int bn = b*NN + n0 + nn;
        float a2 = coef2[o], d2 = coef2[128 + o];
        const float* xr = x2 + (size_t)bn * KNN * CO + o;
        float s = 0.f;
        #pragma unroll
        for (int k = 0; k < KNN; k++)
            s += fmaxf(fmaf(a2, xr[k*CO], d2), 0.f);
        float scv = sc[bn*CO + o];
        float as = coefsc[o], ds = coefsc[128 + o];
        tile[nn*129 + o] = fmaxf(fmaf(as, scv, ds) + s * (1.f/16.f), 0.f);
    }
    __syncthreads();
    #pragma unroll
    for (int i = 0; i < 16; i++) {
        int idx = t + 256*i;
        int nn = idx & 31, o = idx >> 5;
        out[(size_t)b*CO*NN + o*NN + n0 + nn] = tile[nn*129 + o];
    }
}

// ------------------------- host launcher -------------------------------------
extern "C" void kernel_launch(void* const* d_in, const int* in_sizes, int n_in,
                              void* d_out, int out_size) {
    const float* points   = (const float*)d_in[0];
    const float* features = (const float*)d_in[1];
    const float* W0  = (const float*)d_in[2];
    const float* g0  = (const float*)d_in[3];
    const float* b0  = (const float*)d_in[4];
    const float* W1  = (const float*)d_in[5];
    const float* g1  = (const float*)d_in[6];
    const float* b1  = (const float*)d_in[7];
    const float* W2  = (const float*)d_in[8];
    const float* g2  = (const float*)d_in[9];
    const float* b2  = (const float*)d_in[10];
    const float* Wsc = (const float*)d_in[11];
    const float* gsc = (const float*)d_in[12];
    const float* bsc = (const float*)d_in[13];
    float* out = (float*)d_out;

    void *p_idx, *p_center, *p_h, *p_sc, *p_x1, *p_x2, *p_part, *p_partsc, *p_coef;
    cudaGetSymbolAddress(&p_idx,    g_idx);
    cudaGetSymbolAddress(&p_center, g_center);
    cudaGetSymbolAddress(&p_h,      g_h);
    cudaGetSymbolAddress(&p_sc,     g_sc);
    cudaGetSymbolAddress(&p_x1,     g_x1);
    cudaGetSymbolAddress(&p_x2,     g_x2);
    cudaGetSymbolAddress(&p_part,   g_part);
    cudaGetSymbolAddress(&p_partsc, g_partsc);
    cudaGetSymbolAddress(&p_coef,   g_coef);

    int*   idx    = (int*)p_idx;
    float* center = (float*)p_center;
    float* h      = (float*)p_h;
    float* sc     = (float*)p_sc;
    float* x1     = (float*)p_x1;
    float* x2     = (float*)p_x2;
    float* part   = (float*)p_part;
    float* partsc = (float*)p_partsc;
    float* coef0  = (float*)p_coef;
    float* coef1  = coef0 + 256;
    float* coef2  = coef0 + 512;
    float* coef3  = coef0 + 768;

    const float invM  = 1.f / (float)ROWS;
    const float invMs = 1.f / (float)BNROWS;

    knn_kernel<<<GEMM_BLOCKS, 256>>>(points, idx);                          // 0
    feat_kernel<<<BNROWS/16, 128>>>(features, W0, Wsc, center, h, sc);      // 1
    buildstats_kernel<<<GEMM_BLOCKS, 256>>>(center, h, idx, part);          // 2
    colpart_kernel<<<256, 256>>>(sc, partsc);                               // 3
    stats_kernel<<<128, 256>>>(part, GEMM_BLOCKS, g0, b0, coef0, invM);     // 4
    stats_kernel<<<128, 256>>>(partsc, 256, gsc, bsc, coef3, invMs);        // 5
    gemm1_kernel<<<GEMM_BLOCKS, 256>>>(center, h, idx, W1, coef0, x1, part);// 6
    stats_kernel<<<128, 256>>>(part, GEMM_BLOCKS, g1, b1, coef1, invM);     // 7
    gemm2_kernel<<<GEMM_BLOCKS, 256>>>(x1, W2, coef1, x2, part);            // 8
    stats_kernel<<<128, 256>>>(part, GEMM_BLOCKS, g2, b2, coef2, invM);     // 9
    final_kernel<<<1024, 256>>>(x2, sc, coef2, coef3, out);                 // 10
}

// round 7
// speedup vs baseline: 2.9410x; 1.1533x over previous
#include <cuda_runtime.h>
#include <cuda_bf16.h>
#include <math.h>
#include <stdint.h>

// Problem constants
#define BB   32
#define NN   1024
#define CIN  64
#define CO   128
#define KNN  16
#define BNROWS (BB*NN)          // 32768
#define ROWS   (BNROWS*KNN)     // 524288
#define GEMM_BLOCKS (ROWS/128)  // 4096
#define EPSV 1e-5f

// ------------------------- device scratch (static, no allocs) ----------------
static __device__ int   g_idx[ROWS];                  // 2 MB
static __device__ float g_center[BNROWS*CO];          // 16 MB
static __device__ float g_h[BNROWS*CO];               // 16 MB
static __device__ float g_sc[BNROWS*CO];              // 16 MB
static __device__ float g_x1[(size_t)ROWS*CO];        // 268 MB (layer-1 out)
static __device__ float g_x2[(size_t)ROWS*CO];        // 268 MB (layer-2 out)
static __device__ float g_part[GEMM_BLOCKS*256];      // 4 MB
static __device__ float g_partsc[256*256];            // 256 KB
static __device__ float g_coef[4*256];                // (a[128],d[128]) x4

// ------------------------- PTX helpers ---------------------------------------
__device__ __forceinline__ uint32_t smem_u32(const void* p) {
    uint32_t a;
    asm("{ .reg .u64 t; cvta.to.shared.u64 t, %1; cvt.u32.u64 %0, t; }" : "=r"(a) : "l"(p));
    return a;
}
__device__ __forceinline__ void ldsm4(uint32_t* r, uint32_t addr) {
    asm volatile("ldmatrix.sync.aligned.m8n8.x4.shared.b16 {%0,%1,%2,%3}, [%4];"
        : "=r"(r[0]), "=r"(r[1]), "=r"(r[2]), "=r"(r[3]) : "r"(addr));
}
__device__ __forceinline__ void mma_bf16(float* c, const uint32_t* a, uint32_t b0, uint32_t b1) {
    asm volatile("mma.sync.aligned.m16n8k16.row.col.f32.bf16.bf16.f32 "
        "{%0,%1,%2,%3}, {%4,%5,%6,%7}, {%8,%9}, {%0,%1,%2,%3};"
        : "+f"(c[0]), "+f"(c[1]), "+f"(c[2]), "+f"(c[3])
        : "r"(a[0]), "r"(a[1]), "r"(a[2]), "r"(a[3]), "r"(b0), "r"(b1));
}

// ------------------------- 1) kNN: warp per query, register-resident ---------
__global__ __launch_bounds__(256)
void knn_kernel(const float* __restrict__ pts, int* __restrict__ idxout) {
    __shared__ float sx[NN], sy[NN], sz[NN], sxx[NN];
    int t = threadIdx.x;
    int wid = t >> 5, lane = t & 31;
    int blk = blockIdx.x;
    int b = blk >> 7;
    int n = ((blk & 127) << 3) + wid;
    const float* P = pts + (size_t)b * 3 * NN;
    for (int m = t; m < NN; m += 256) {
        float x = P[m], y = P[NN + m], z = P[2*NN + m];
        sx[m] = x; sy[m] = y; sz[m] = z;
        sxx[m] = x*x + y*y + z*z;
    }
    __syncthreads();
    float qx = sx[n], qy = sy[n], qz = sz[n], qxx = sxx[n];
    float d[32];
    #pragma unroll
    for (int j = 0; j < 32; j++) {
        int m = j*32 + lane;
        float dd = 2.f*(qx*sx[m] + qy*sy[m] + qz*sz[m]) - qxx - sxx[m];
        d[j] = (m == n) ? -INFINITY : dd;
    }
    int* op = idxout + ((size_t)b*NN + n) * KNN;
    unsigned alive = 0xffffffffu;
    for (int r = 0; r < KNN; r++) {
        float bv = -INFINITY; int bj = 0;
        #pragma unroll
        for (int j = 0; j < 32; j++) {
            float dj = (alive & (1u << j)) ? d[j] : -INFINITY;
            if (dj > bv) { bv = dj; bj = j; }
        }
        int bi = bj*32 + lane;
        #pragma unroll
        for (int s = 16; s > 0; s >>= 1) {
            float ov = __shfl_down_sync(0xffffffffu, bv, s);
            int   oi = __shfl_down_sync(0xffffffffu, bi, s);
            if (ov > bv || (ov == bv && oi < bi)) { bv = ov; bi = oi; }
        }
        bi = __shfl_sync(0xffffffffu, bi, 0);
        if (lane == 0) op[r] = bi;
        if ((bi & 31) == lane) alive &= ~(1u << (bi >> 5));
    }
}

// ------------------------- 2) per-point GEMVs --------------------------------
__global__ void feat_kernel(const float* __restrict__ f,
                            const float* __restrict__ W0,
                            const float* __restrict__ Wsc,
                            float* __restrict__ center,
                            float* __restrict__ h,
                            float* __restrict__ sc) {
    __shared__ float fs[CIN][16];
    int base = blockIdx.x * 16;
    int b = base >> 10, n0 = base & 1023;
    int t = threadIdx.x;
    #pragma unroll
    for (int i = 0; i < 8; i++) {
        int idx = t + 128*i;
        int c = idx >> 4, j = idx & 15;
        fs[c][j] = f[(size_t)b*CIN*NN + c*NN + n0 + j];
    }
    __syncthreads();
    int o = t;
    float ctr[16], hh[16], ss[16];
    #pragma unroll
    for (int j = 0; j < 16; j++) { ctr[j]=0.f; hh[j]=0.f; ss[j]=0.f; }
    for (int c = 0; c < CIN; c++) {
        float w0a = W0[o*128 + c];
        float w0b = W0[o*128 + 64 + c];
        float ws  = Wsc[o*64 + c];
        float wc  = w0a - w0b;
        const float* fr = fs[c];
        #pragma unroll
        for (int j = 0; j < 16; j++) {
            float fv = fr[j];
            ctr[j] = fmaf(wc,  fv, ctr[j]);
            hh[j]  = fmaf(w0b, fv, hh[j]);
            ss[j]  = fmaf(ws,  fv, ss[j]);
        }
    }
    #pragma unroll
    for (int j = 0; j < 16; j++) {
        int row = base + j;
        center[row*CO + o] = ctr[j];
        h[row*CO + o]      = hh[j];
        sc[row*CO + o]     = ss[j];
    }
}

// ------------------------- 3) layer-0 stats only -----------------------------
__global__ void buildstats_kernel(const float* __restrict__ center,
                                  const float* __restrict__ h,
                                  const int* __restrict__ idx,
                                  float* __restrict__ part) {
    __shared__ float red[8][132];
    int t = threadIdx.x;
    int oq = (t & 31) << 2;
    int strip = t >> 5;
    int bn = blockIdx.x * 8 + strip;
    int b = bn >> 10;
    float4 c4 = *reinterpret_cast<const float4*>(&center[bn*CO + oq]);
    const int* ip = idx + bn*KNN;
    float s0=0,s1=0,s2=0,s3=0, q0=0,q1=0,q2=0,q3=0;
    #pragma unroll
    for (int k = 0; k < KNN; k++) {
        int gi = ip[k];
        float4 h4 = *reinterpret_cast<const float4*>(&h[(b*NN + gi)*CO + oq]);
        float vx = c4.x + h4.x, vy = c4.y + h4.y, vz = c4.z + h4.z, vw = c4.w + h4.w;
        s0 += vx; s1 += vy; s2 += vz; s3 += vw;
        q0 = fmaf(vx,vx,q0); q1 = fmaf(vy,vy,q1); q2 = fmaf(vz,vz,q2); q3 = fmaf(vw,vw,q3);
    }
    red[strip][oq+0]=s0; red[strip][oq+1]=s1; red[strip][oq+2]=s2; red[strip][oq+3]=s3;
    __syncthreads();
    if (t < 128) {
        float s = 0;
        #pragma unroll
        for (int q = 0; q < 8; q++) s += red[q][t];
        part[blockIdx.x*256 + t] = s;
    }
    __syncthreads();
    red[strip][oq+0]=q0; red[strip][oq+1]=q1; red[strip][oq+2]=q2; red[strip][oq+3]=q3;
    __syncthreads();
    if (t < 128) {
        float s = 0;
        #pragma unroll
        for (int q = 0; q < 8; q++) s += red[q][t];
        part[blockIdx.x*256 + 128 + t] = s;
    }
}

// ------------------------- 4) stats: partials -> (a, d) ----------------------
__global__ void stats_kernel(const float* __restrict__ part, int nparts,
                             const float* __restrict__ g, const float* __restrict__ bt,
                             float* __restrict__ coef, float invM) {
    __shared__ float ss[256], qq[256];
    int o = blockIdx.x, t = threadIdx.x;
    float s = 0.f, q = 0.f;
    for (int p = t; p < nparts; p += 256) {
        s += part[p*256 + o];
        q += part[p*256 + 128 + o];
    }
    ss[t] = s; qq[t] = q;
    __syncthreads();
    for (int st = 128; st > 0; st >>= 1) {
        if (t < st) { ss[t] += ss[t+st]; qq[t] += qq[t+st]; }
        __syncthreads();
    }
    if (t == 0) {
        float mean = ss[0] * invM;
        float var  = qq[0] * invM - mean*mean;
        float a = g[o] / sqrtf(var + EPSV);
        coef[o] = a;
        coef[128 + o] = bt[o] - mean * a;
    }
}

// coalesced partial-sum over sc (rows x 128), 128 rows per block
__global__ void colpart_kernel(const float* __restrict__ X, float* __restrict__ part) {
    __shared__ float sm0[2][128], sm1[2][128];
    int t = threadIdx.x;
    int o = t & 127, hf = t >> 7;
    int r0 = blockIdx.x * 128 + hf * 64;
    float s = 0.f, q = 0.f;
    for (int i = 0; i < 64; i++) {
        float v = X[(size_t)(r0 + i)*CO + o];
        s += v; q = fmaf(v, v, q);
    }
    sm0[hf][o] = s; sm1[hf][o] = q;
    __syncthreads();
    if (t < 128) {
        part[blockIdx.x*256 + t]       = sm0[0][t] + sm0[1][t];
        part[blockIdx.x*256 + 128 + t] = sm1[0][t] + sm1[1][t];
    }
}

// ------------------------- mma.sync bf16 3x GEMM core ------------------------
// 256 threads, tile 128m x 128n, K=128 in 4 quarters of 32 (2 k16 steps each).
// Warp grid 2m x 4n, warp tile 64m x 32n. 3xBF16: D += Ah*Bh + Al*Bh + Ah*Bl.
#define ASTRIDE 40   // bf16 elems per row (80 B), conflict-free ldmatrix

struct __align__(16) TCSmem {
    __nv_bfloat16 Ahi[128*ASTRIDE];
    __nv_bfloat16 Alo[128*ASTRIDE];
    __nv_bfloat16 Bhi[128*ASTRIDE];
    __nv_bfloat16 Blo[128*ASTRIDE];
    float sa[128], sd[128];
    int offC[128], offH[128];
};

__device__ __forceinline__ void bf16split(float v, __nv_bfloat16& hi, __nv_bfloat16& lo) {
    hi = __float2bfloat16_rn(v);
    lo = __float2bfloat16_rn(v - __bfloat162float(hi));
}

__device__ __forceinline__ void gemm_mma_core(
    bool fused, const float* __restrict__ X,
    const float* __restrict__ center, const float* __restrict__ h,
    const int* __restrict__ idx,
    const float* __restrict__ W, const float* __restrict__ coef,
    float* __restrict__ Y, float* __restrict__ part)
{
    __shared__ TCSmem S;
    int t = threadIdx.x;
    int wid = t >> 5, lane = t & 31;
    int wm = wid >> 2, wn = wid & 3;       // warp grid 2m x 4n
    int m0w = wm * 64, n0w = wn * 32;
    int g = lane >> 2, q = lane & 3;
    size_t mbase = (size_t)blockIdx.x * 128;

    if (t < 128) {
        S.sa[t] = coef[t];
        S.sd[t] = coef[128 + t];
        if (fused) {
            int G = (int)mbase + t;
            int bn = G >> 4;
            int gi = idx[G];
            S.offC[t] = bn * CO;
            S.offH[t] = ((bn >> 10) * NN + gi) * CO;
        }
    }
    __syncthreads();

    // per-lane ldmatrix base offsets (bytes)
    uint32_t aBaseHi = smem_u32(S.Ahi) + (uint32_t)((m0w + (lane & 15)) * 80 + ((lane >> 4) << 4));
    uint32_t aBaseLo = aBaseHi + (uint32_t)(128*ASTRIDE*2);
    uint32_t bRow = (uint32_t)(n0w + (lane & 7) + ((lane >> 4) << 3));
    uint32_t bBaseHi = smem_u32(S.Bhi) + bRow * 80 + (((lane >> 3) & 1) << 4);
    uint32_t bBaseLo = bBaseHi + (uint32_t)(128*ASTRIDE*2);

    float acc[4][4][4];
    #pragma unroll
    for (int a = 0; a < 4; a++)
        #pragma unroll
        for (int b = 0; b < 4; b++)
            #pragma unroll
            for (int r = 0; r < 4; r++) acc[a][b][r] = 0.f;

    for (int kq = 0; kq < 4; kq++) {
        int cq = kq * 32;
        // build A quarter (128 x 32) hi/lo
        #pragma unroll 4
        for (int i = 0; i < 16; i++) {
            int e = t + 256*i;
            int c = e & 31, m = e >> 5;
            float v;
            if (fused)
                v = center[S.offC[m] + cq + c] + h[S.offH[m] + cq + c];
            else
                v = X[(mbase + m)*CO + cq + c];
            v = fmaxf(fmaf(S.sa[cq + c], v, S.sd[cq + c]), 0.f);
            __nv_bfloat16 hi, lo; bf16split(v, hi, lo);
            S.Ahi[m*ASTRIDE + c] = hi;
            S.Alo[m*ASTRIDE + c] = lo;
        }
        // build B quarter
        #pragma unroll 4
        for (int i = 0; i < 16; i++) {
            int e = t + 256*i;
            int c = e & 31, o = e >> 5;
            float w = W[o*CO + cq + c];
            __nv_bfloat16 hi, lo; bf16split(w, hi, lo);
            S.Bhi[o*ASTRIDE + c] = hi;
            S.Blo[o*ASTRIDE + c] = lo;
        }
        __syncthreads();

        #pragma unroll
        for (int ks = 0; ks < 2; ks++) {
            uint32_t koff = (uint32_t)(ks * 32);   // 16 bf16 = 32 B
            uint32_t ahi[4][4], alo[4][4];
            #pragma unroll
            for (int a = 0; a < 4; a++) {
                ldsm4(ahi[a], aBaseHi + (uint32_t)(a*16*80) + koff);
                ldsm4(alo[a], aBaseLo + (uint32_t)(a*16*80) + koff);
            }
            #pragma unroll
            for (int bp = 0; bp < 2; bp++) {
                uint32_t bh[4], bl[4];
                ldsm4(bh, bBaseHi + (uint32_t)(bp*16*80) + koff);
                ldsm4(bl, bBaseLo + (uint32_t)(bp*16*80) + koff);
                #pragma unroll
                for (int a = 0; a < 4; a++) {
                    #pragma unroll
                    for (int bb = 0; bb < 2; bb++) {
                        float* c = acc[a][2*bp + bb];
                        mma_bf16(c, ahi[a], bh[2*bb], bh[2*bb+1]);
                        mma_bf16(c, alo[a], bh[2*bb], bh[2*bb+1]);
                        mma_bf16(c, ahi[a], bl[2*bb], bl[2*bb+1]);
                    }
                }
            }
        }
        __syncthreads();
    }

    // epilogue: store Y + BN partials
    float ls[4][2], lq[4][2];
    #pragma unroll
    for (int b = 0; b < 4; b++) { ls[b][0]=0.f; ls[b][1]=0.f; lq[b][0]=0.f; lq[b][1]=0.f; }
    #pragma unroll
    for (int a = 0; a < 4; a++) {
        #pragma unroll
        for (int hf = 0; hf < 2; hf++) {
            int row = m0w + 16*a + g + 8*hf;
            float* yr = Y + (mbase + row)*CO + n0w + 2*q;
            #pragma unroll
            for (int b = 0; b < 4; b++) {
                float c0 = acc[a][b][2*hf], c1 = acc[a][b][2*hf + 1];
                *reinterpret_cast<float2*>(yr + 8*b) = make_float2(c0, c1);
                ls[b][0] += c0; ls[b][1] += c1;
                lq[b][0] = fmaf(c0, c0, lq[b][0]);
                lq[b][1] = fmaf(c1, c1, lq[b][1]);
            }
        }
    }
    // reduce over g (lanes differing in bits 2..4)
    #pragma unroll
    for (int b = 0; b < 4; b++) {
        #pragma unroll
        for (int p = 0; p < 2; p++) {
            #pragma unroll
            for (int off = 4; off < 32; off <<= 1) {
                ls[b][p] += __shfl_xor_sync(0xffffffffu, ls[b][p], off);
                lq[b][p] += __shfl_xor_sync(0xffffffffu, lq[b][p], off);
            }
        }
    }
    float* redS = reinterpret_cast<float*>(S.Ahi);            // [8][32] overlay
    float* redQ = reinterpret_cast<float*>(S.Alo);
    if (lane < 4) {
        #pragma unroll
        for (int b = 0; b < 4; b++) {
            #pragma unroll
            for (int p = 0; p < 2; p++) {
                int cs = 8*b + 2*lane + p;
                redS[wid*32 + cs] = ls[b][p];
                redQ[wid*32 + cs] = lq[b][p];
            }
        }
    }
    __syncthreads();
    if (t < 128) {
        int wnc = t >> 5, cw = t & 31;
        float Sv = redS[wnc*32 + cw] + redS[(wnc+4)*32 + cw];
        float Qv = redQ[wnc*32 + cw] + redQ[(wnc+4)*32 + cw];
        part[blockIdx.x*256 + t]       = Sv;
        part[blockIdx.x*256 + 128 + t] = Qv;
    }
}

__global__ __launch_bounds__(256, 2)
void gemm1_mma(const float* __restrict__ center, const float* __restrict__ h,
               const int* __restrict__ idx, const float* __restrict__ W,
               const float* __restrict__ coef, float* __restrict__ Y,
               float* __restrict__ part) {
    gemm_mma_core(true, nullptr, center, h, idx, W, coef, Y, part);
}

__global__ __launch_bounds__(256, 2)
void gemm2_mma(const float* __restrict__ X, const float* __restrict__ W,
               const float* __restrict__ coef, float* __restrict__ Y,
               float* __restrict__ part) {
    gemm_mma_core(false, X, nullptr, nullptr, nullptr, W, coef, Y, part);
}

// ------------------------- final: mean_k relu(bn2) + bn_sc + relu, transpose -
__global__ void final_kernel(const float* __restrict__ x2, const float* __restrict__ sc,
                             const float* __restrict__ coef2, const float* __restrict__ coefsc,
                             float* __restrict__ out) {
    __shared__ float tile[32*129];
    int t = threadIdx.x;
    int blk = blockIdx.x;
    int b = blk >> 5;
    int n0 = (blk & 31) << 5;
    #pragma unroll
    for (int i = 0; i < 16; i++) {
        int idx = t + 256*i;
        int o = idx & 127, nn = idx >> 7;
        int bn = b*NN + n0 + nn;
        float a2 = coef2[o], d2 = coef2[128 + o];
        const float* xr = x2 + (size_t)bn * KNN * CO + o;
        float s = 0.f;
        #pragma unroll
        for (int k = 0; k < KNN; k++)
            s += fmaxf(fmaf(a2, xr[k*CO], d2), 0.f);
        float scv = sc[bn*CO + o];
        float as = coefsc[o], ds = coefsc[128 + o];
        tile[nn*129 + o] = fmaxf(fmaf(as, scv, ds) + s * (1.f/16.f), 0.f);
    }
    __syncthreads();
    #pragma unroll
    for (int i = 0; i < 16; i++) {
        int idx = t + 256*i;
        int nn = idx & 31, o = idx >> 5;
        out[(size_t)b*CO*NN + o*NN + n0 + nn] = tile[nn*129 + o];
    }
}

// ------------------------- host launcher -------------------------------------
extern "C" void kernel_launch(void* const* d_in, const int* in_sizes, int n_in,
                              void* d_out, int out_size) {
    const float* points   = (const float*)d_in[0];
    const float* features = (const float*)d_in[1];
    const float* W0  = (const float*)d_in[2];
    const float* g0  = (const float*)d_in[3];
    const float* b0  = (const float*)d_in[4];
    const float* W1  = (const float*)d_in[5];
    const float* g1  = (const float*)d_in[6];
    const float* b1  = (const float*)d_in[7];
    const float* W2  = (const float*)d_in[8];
    const float* g2  = (const float*)d_in[9];
    const float* b2  = (const float*)d_in[10];
    const float* Wsc = (const float*)d_in[11];
    const float* gsc = (const float*)d_in[12];
    const float* bsc = (const float*)d_in[13];
    float* out = (float*)d_out;

    void *p_idx, *p_center, *p_h, *p_sc, *p_x1, *p_x2, *p_part, *p_partsc, *p_coef;
    cudaGetSymbolAddress(&p_idx,    g_idx);
    cudaGetSymbolAddress(&p_center, g_center);
    cudaGetSymbolAddress(&p_h,      g_h);
    cudaGetSymbolAddress(&p_sc,     g_sc);
    cudaGetSymbolAddress(&p_x1,     g_x1);
    cudaGetSymbolAddress(&p_x2,     g_x2);
    cudaGetSymbolAddress(&p_part,   g_part);
    cudaGetSymbolAddress(&p_partsc, g_partsc);
    cudaGetSymbolAddress(&p_coef,   g_coef);

    int*   idx    = (int*)p_idx;
    float* center = (float*)p_center;
    float* h      = (float*)p_h;
    float* sc     = (float*)p_sc;
    float* x1     = (float*)p_x1;
    float* x2     = (float*)p_x2;
    float* part   = (float*)p_part;
    float* partsc = (float*)p_partsc;
    float* coef0  = (float*)p_coef;
    float* coef1  = coef0 + 256;
    float* coef2  = coef0 + 512;
    float* coef3  = coef0 + 768;

    const float invM  = 1.f / (float)ROWS;
    const float invMs = 1.f / (float)BNROWS;

    knn_kernel<<<GEMM_BLOCKS, 256>>>(points, idx);
    feat_kernel<<<BNROWS/16, 128>>>(features, W0, Wsc, center, h, sc);
    buildstats_kernel<<<GEMM_BLOCKS, 256>>>(center, h, idx, part);
    colpart_kernel<<<256, 256>>>(sc, partsc);
    stats_kernel<<<128, 256>>>(part, GEMM_BLOCKS, g0, b0, coef0, invM);
    stats_kernel<<<128, 256>>>(partsc, 256, gsc, bsc, coef3, invMs);
    gemm1_mma<<<GEMM_BLOCKS, 256>>>(center, h, idx, W1, coef0, x1, part);
    stats_kernel<<<128, 256>>>(part, GEMM_BLOCKS, g1, b1, coef1, invM);
    gemm2_mma<<<GEMM_BLOCKS, 256>>>(x1, W2, coef1, x2, part);
    stats_kernel<<<128, 256>>>(part, GEMM_BLOCKS, g2, b2, coef2, invM);
    final_kernel<<<1024, 256>>>(x2, sc, coef2, coef3, out);
}

// round 8
// speedup vs baseline: 4.0186x; 1.3664x over previous
#include <cuda_runtime.h>
#include <cuda_bf16.h>
#include <math.h>
#include <stdint.h>

// Problem constants
#define BB   32
#define NN   1024
#define CIN  64
#define CO   128
#define KNN  16
#define BNROWS (BB*NN)          // 32768
#define ROWS   (BNROWS*KNN)     // 524288
#define GEMM_BLOCKS (ROWS/128)  // 4096
#define EPSV 1e-5f

// ------------------------- device scratch (static, no allocs) ----------------
static __device__ int   g_idx[ROWS];                  // 2 MB
static __device__ float g_center[BNROWS*CO];          // 16 MB
static __device__ float g_h[BNROWS*CO];               // 16 MB
static __device__ float g_sc[BNROWS*CO];              // 16 MB
static __device__ float g_x1[(size_t)ROWS*CO];        // 268 MB (layer-1 out)
static __device__ float g_x2[(size_t)ROWS*CO];        // 268 MB (layer-2 out)
static __device__ float g_part[GEMM_BLOCKS*256];      // 4 MB
static __device__ float g_partsc[256*256];            // 256 KB
static __device__ float g_coef[4*256];                // (a[128],d[128]) x4
static __device__ __nv_bfloat16 g_w1hi[CO*CO], g_w1lo[CO*CO];
static __device__ __nv_bfloat16 g_w2hi[CO*CO], g_w2lo[CO*CO];

// ------------------------- PTX helpers ---------------------------------------
__device__ __forceinline__ uint32_t smem_u32(const void* p) {
    uint32_t a;
    asm("{ .reg .u64 t; cvta.to.shared.u64 t, %1; cvt.u32.u64 %0, t; }" : "=r"(a) : "l"(p));
    return a;
}
__device__ __forceinline__ void ldsm4(uint32_t* r, uint32_t addr) {
    asm volatile("ldmatrix.sync.aligned.m8n8.x4.shared.b16 {%0,%1,%2,%3}, [%4];"
        : "=r"(r[0]), "=r"(r[1]), "=r"(r[2]), "=r"(r[3]) : "r"(addr));
}
__device__ __forceinline__ void mma_bf16(float* c, const uint32_t* a, uint32_t b0, uint32_t b1) {
    asm volatile("mma.sync.aligned.m16n8k16.row.col.f32.bf16.bf16.f32 "
        "{%0,%1,%2,%3}, {%4,%5,%6,%7}, {%8,%9}, {%0,%1,%2,%3};"
        : "+f"(c[0]), "+f"(c[1]), "+f"(c[2]), "+f"(c[3])
        : "r"(a[0]), "r"(a[1]), "r"(a[2]), "r"(a[3]), "r"(b0), "r"(b1));
}
__device__ __forceinline__ uint32_t packbf2(__nv_bfloat16 lo, __nv_bfloat16 hi) {
    return (uint32_t)__bfloat16_as_ushort(lo) | ((uint32_t)__bfloat16_as_ushort(hi) << 16);
}

// ------------------------- dynamic smem layout (bytes) ------------------------
// B (full K, resident): rows stride 136 bf16 = 272 B -> ldmatrix conflict-free
#define DB_BHI   0          // 128*272 = 34816
#define DB_BLO   34816      // 34816
#define DB_A     69632      // 2 bufs x (hi 10240 + lo 10240) = 40960
#define DB_SA    110592     // 512
#define DB_SD    111104     // 512
#define DB_OFFC  111616     // 512
#define DB_OFFH  112128     // 512
#define DB_TOTAL 112640

// ------------------------- 0) W hi/lo precompute ------------------------------
__global__ void whilo_kernel(const float* __restrict__ W1, const float* __restrict__ W2,
                             __nv_bfloat16* __restrict__ w1hi, __nv_bfloat16* __restrict__ w1lo,
                             __nv_bfloat16* __restrict__ w2hi, __nv_bfloat16* __restrict__ w2lo) {
    int i = blockIdx.x * 256 + threadIdx.x;   // 16384
    float a = W1[i];
    __nv_bfloat16 h = __float2bfloat16_rn(a);
    w1hi[i] = h; w1lo[i] = __float2bfloat16_rn(a - __bfloat162float(h));
    float b = W2[i];
    __nv_bfloat16 h2 = __float2bfloat16_rn(b);
    w2hi[i] = h2; w2lo[i] = __float2bfloat16_rn(b - __bfloat162float(h2));
}

// ------------------------- 1) kNN: warp per query, register-resident ---------
__global__ __launch_bounds__(256)
void knn_kernel(const float* __restrict__ pts, int* __restrict__ idxout) {
    __shared__ float sx[NN], sy[NN], sz[NN], sxx[NN];
    int t = threadIdx.x;
    int wid = t >> 5, lane = t & 31;
    int blk = blockIdx.x;
    int b = blk >> 7;
    int n = ((blk & 127) << 3) + wid;
    const float* P = pts + (size_t)b * 3 * NN;
    for (int m = t; m < NN; m += 256) {
        float x = P[m], y = P[NN + m], z = P[2*NN + m];
        sx[m] = x; sy[m] = y; sz[m] = z;
        sxx[m] = x*x + y*y + z*z;
    }
    __syncthreads();
    float qx = sx[n], qy = sy[n], qz = sz[n], qxx = sxx[n];
    float d[32];
    #pragma unroll
    for (int j = 0; j < 32; j++) {
        int m = j*32 + lane;
        float dd = 2.f*(qx*sx[m] + qy*sy[m] + qz*sz[m]) - qxx - sxx[m];
        d[j] = (m == n) ? -INFINITY : dd;
    }
    int* op = idxout + ((size_t)b*NN + n) * KNN;
    unsigned alive = 0xffffffffu;
    for (int r = 0; r < KNN; r++) {
        float bv = -INFINITY; int bj = 0;
        #pragma unroll
        for (int j = 0; j < 32; j++) {
            float dj = (alive & (1u << j)) ? d[j] : -INFINITY;
            if (dj > bv) { bv = dj; bj = j; }
        }
        int bi = bj*32 + lane;
        #pragma unroll
        for (int s = 16; s > 0; s >>= 1) {
            float ov = __shfl_down_sync(0xffffffffu, bv, s);
            int   oi = __shfl_down_sync(0xffffffffu, bi, s);
            if (ov > bv || (ov == bv && oi < bi)) { bv = ov; bi = oi; }
        }
        bi = __shfl_sync(0xffffffffu, bi, 0);
        if (lane == 0) op[r] = bi;
        if ((bi & 31) == lane) alive &= ~(1u << (bi >> 5));
    }
}

// ------------------------- 2) per-point GEMVs --------------------------------
__global__ void feat_kernel(const float* __restrict__ f,
                            const float* __restrict__ W0,
                            const float* __restrict__ Wsc,
                            float* __restrict__ center,
                            float* __restrict__ h,
                            float* __restrict__ sc) {
    __shared__ float fs[CIN][16];
    int base = blockIdx.x * 16;
    int b = base >> 10, n0 = base & 1023;
    int t = threadIdx.x;
    #pragma unroll
    for (int i = 0; i < 8; i++) {
        int idx = t + 128*i;
        int c = idx >> 4, j = idx & 15;
        fs[c][j] = f[(size_t)b*CIN*NN + c*NN + n0 + j];
    }
    __syncthreads();
    int o = t;
    float ctr[16], hh[16], ss[16];
    #pragma unroll
    for (int j = 0; j < 16; j++) { ctr[j]=0.f; hh[j]=0.f; ss[j]=0.f; }
    for (int c = 0; c < CIN; c++) {
        float w0a = W0[o*128 + c];
        float w0b = W0[o*128 + 64 + c];
        float ws  = Wsc[o*64 + c];
        float wc  = w0a - w0b;
        const float* fr = fs[c];
        #pragma unroll
        for (int j = 0; j < 16; j++) {
            float fv = fr[j];
            ctr[j] = fmaf(wc,  fv, ctr[j]);
            hh[j]  = fmaf(w0b, fv, hh[j]);
            ss[j]  = fmaf(ws,  fv, ss[j]);
        }
    }
    #pragma unroll
    for (int j = 0; j < 16; j++) {
        int row = base + j;
        center[row*CO + o] = ctr[j];
        h[row*CO + o]      = hh[j];
        sc[row*CO + o]     = ss[j];
    }
}

// ------------------------- 3) layer-0 stats only -----------------------------
__global__ void buildstats_kernel(const float* __restrict__ center,
                                  const float* __restrict__ h,
                                  const int* __restrict__ idx,
                                  float* __restrict__ part) {
    __shared__ float red[8][132];
    int t = threadIdx.x;
    int oq = (t & 31) << 2;
    int strip = t >> 5;
    int bn = blockIdx.x * 8 + strip;
    int b = bn >> 10;
    float4 c4 = *reinterpret_cast<const float4*>(&center[bn*CO + oq]);
    const int* ip = idx + bn*KNN;
    float s0=0,s1=0,s2=0,s3=0, q0=0,q1=0,q2=0,q3=0;
    #pragma unroll
    for (int k = 0; k < KNN; k++) {
        int gi = ip[k];
        float4 h4 = *reinterpret_cast<const float4*>(&h[(b*NN + gi)*CO + oq]);
        float vx = c4.x + h4.x, vy = c4.y + h4.y, vz = c4.z + h4.z, vw = c4.w + h4.w;
        s0 += vx; s1 += vy; s2 += vz; s3 += vw;
        q0 = fmaf(vx,vx,q0); q1 = fmaf(vy,vy,q1); q2 = fmaf(vz,vz,q2); q3 = fmaf(vw,vw,q3);
    }
    red[strip][oq+0]=s0; red[strip][oq+1]=s1; red[strip][oq+2]=s2; red[strip][oq+3]=s3;
    __syncthreads();
    if (t < 128) {
        float s = 0;
        #pragma unroll
        for (int q = 0; q < 8; q++) s += red[q][t];
        part[blockIdx.x*256 + t] = s;
    }
    __syncthreads();
    red[strip][oq+0]=q0; red[strip][oq+1]=q1; red[strip][oq+2]=q2; red[strip][oq+3]=q3;
    __syncthreads();
    if (t < 128) {
        float s = 0;
        #pragma unroll
        for (int q = 0; q < 8; q++) s += red[q][t];
        part[blockIdx.x*256 + 128 + t] = s;
    }
}

// ------------------------- 4) stats: partials -> (a, d) ----------------------
__global__ void stats_kernel(const float* __restrict__ part, int nparts,
                             const float* __restrict__ g, const float* __restrict__ bt,
                             float* __restrict__ coef, float invM) {
    __shared__ float ss[256], qq[256];
    int o = blockIdx.x, t = threadIdx.x;
    float s = 0.f, q = 0.f;
    for (int p = t; p < nparts; p += 256) {
        s += part[p*256 + o];
        q += part[p*256 + 128 + o];
    }
    ss[t] = s; qq[t] = q;
    __syncthreads();
    for (int st = 128; st > 0; st >>= 1) {
        if (t < st) { ss[t] += ss[t+st]; qq[t] += qq[t+st]; }
        __syncthreads();
    }
    if (t == 0) {
        float mean = ss[0] * invM;
        float var  = qq[0] * invM - mean*mean;
        float a = g[o] / sqrtf(var + EPSV);
        coef[o] = a;
        coef[128 + o] = bt[o] - mean * a;
    }
}

// coalesced partial-sum over sc (rows x 128), 128 rows per block
__global__ void colpart_kernel(const float* __restrict__ X, float* __restrict__ part) {
    __shared__ float sm0[2][128], sm1[2][128];
    int t = threadIdx.x;
    int o = t & 127, hf = t >> 7;
    int r0 = blockIdx.x * 128 + hf * 64;
    float s = 0.f, q = 0.f;
    for (int i = 0; i < 64; i++) {
        float v = X[(size_t)(r0 + i)*CO + o];
        s += v; q = fmaf(v, v, q);
    }
    sm0[hf][o] = s; sm1[hf][o] = q;
    __syncthreads();
    if (t < 128) {
        part[blockIdx.x*256 + t]       = sm0[0][t] + sm0[1][t];
        part[blockIdx.x*256 + 128 + t] = sm1[0][t] + sm1[1][t];
    }
}

// ------------------------- pipelined mma.sync bf16 3x GEMM -------------------
// 256 threads, tile 128m x 128n, K=128. B (hi/lo) fully smem-resident.
// A quarters (32 k) double-buffered: prefetch LDG -> mma -> cvt+STS.
__device__ __forceinline__ void a_prefetch(float4* rx, bool fused,
                                           const float* __restrict__ X,
                                           const float* __restrict__ h,
                                           const int* offH, size_t mbase, int cq, int t) {
    #pragma unroll
    for (int i = 0; i < 4; i++) {
        int e = t + 256*i;
        int c4 = e & 7, m = e >> 3;
        const float* src = fused ? (h + offH[m] + cq + c4*4)
                                 : (X + (mbase + m)*CO + cq + c4*4);
        rx[i] = *reinterpret_cast<const float4*>(src);
    }
}

__device__ __forceinline__ void a_convert(const float4* rx, bool fused,
                                          const float* __restrict__ center, const int* offC,
                                          char* bufHi, char* bufLo,
                                          const float* sa, const float* sd, int cq, int t) {
    #pragma unroll
    for (int i = 0; i < 4; i++) {
        int e = t + 256*i;
        int c4 = e & 7, m = e >> 3;
        int c0 = c4*4;
        float v0 = rx[i].x, v1 = rx[i].y, v2 = rx[i].z, v3 = rx[i].w;
        if (fused) {
            float4 cv = *reinterpret_cast<const float4*>(center + offC[m] + cq + c0);
            v0 += cv.x; v1 += cv.y; v2 += cv.z; v3 += cv.w;
        }
        v0 = fmaxf(fmaf(sa[cq+c0+0], v0, sd[cq+c0+0]), 0.f);
        v1 = fmaxf(fmaf(sa[cq+c0+1], v1, sd[cq+c0+1]), 0.f);
        v2 = fmaxf(fmaf(sa[cq+c0+2], v2, sd[cq+c0+2]), 0.f);
        v3 = fmaxf(fmaf(sa[cq+c0+3], v3, sd[cq+c0+3]), 0.f);
        __nv_bfloat16 h0 = __float2bfloat16_rn(v0), h1 = __float2bfloat16_rn(v1);
        __nv_bfloat16 h2 = __float2bfloat16_rn(v2), h3 = __float2bfloat16_rn(v3);
        __nv_bfloat16 l0 = __float2bfloat16_rn(v0 - __bfloat162float(h0));
        __nv_bfloat16 l1 = __float2bfloat16_rn(v1 - __bfloat162float(h1));
        __nv_bfloat16 l2 = __float2bfloat16_rn(v2 - __bfloat162float(h2));
        __nv_bfloat16 l3 = __float2bfloat16_rn(v3 - __bfloat162float(h3));
        *reinterpret_cast<uint2*>(bufHi + m*80 + c0*2) =
            make_uint2(packbf2(h0, h1), packbf2(h2, h3));
        *reinterpret_cast<uint2*>(bufLo + m*80 + c0*2) =
            make_uint2(packbf2(l0, l1), packbf2(l2, l3));
    }
}

__device__ __forceinline__ void gemm_mma_core(
    bool fused, const float* __restrict__ X,
    const float* __restrict__ center, const float* __restrict__ h,
    const int* __restrict__ idx,
    const __nv_bfloat16* __restrict__ Whi, const __nv_bfloat16* __restrict__ Wlo,
    const float* __restrict__ coef,
    float* __restrict__ Y, float* __restrict__ part)
{
    extern __shared__ char smem[];
    int t = threadIdx.x;
    int wid = t >> 5, lane = t & 31;
    int wm = wid >> 2, wn = wid & 3;       // warp grid 2m x 4n
    int m0w = wm * 64, n0w = wn * 32;
    int g = lane >> 2, q = lane & 3;
    size_t mbase = (size_t)blockIdx.x * 128;

    float* sa = (float*)(smem + DB_SA);
    float* sd = (float*)(smem + DB_SD);
    int* offC = (int*)(smem + DB_OFFC);
    int* offH = (int*)(smem + DB_OFFH);

    if (t < 128) {
        sa[t] = coef[t];
        sd[t] = coef[128 + t];
        if (fused) {
            int G = (int)mbase + t;
            int bn = G >> 4;
            int gi = idx[G];
            offC[t] = bn * CO;
            offH[t] = ((bn >> 10) * NN + gi) * CO;
        }
    }
    // load whole B (hi/lo) into smem, rows stride 136 bf16 (68 u32)
    {
        const uint32_t* wh = reinterpret_cast<const uint32_t*>(Whi);
        const uint32_t* wl = reinterpret_cast<const uint32_t*>(Wlo);
        uint32_t* bh = reinterpret_cast<uint32_t*>(smem + DB_BHI);
        uint32_t* bl = reinterpret_cast<uint32_t*>(smem + DB_BLO);
        #pragma unroll
        for (int i = 0; i < 32; i++) {
            int e = t + 256*i;          // 8192 u32
            int c2 = e & 63, o = e >> 6;
            bh[o*68 + c2] = wh[e];
            bl[o*68 + c2] = wl[e];
        }
    }
    __syncthreads();

    // build quarter 0 into buf 0
    {
        float4 rx[4];
        a_prefetch(rx, fused, X, h, offH, mbase, 0, t);
        a_convert(rx, fused, center, offC, smem + DB_A, smem + DB_A + 10240, sa, sd, 0, t);
    }
    __syncthreads();

    uint32_t sb = smem_u32(smem);
    uint32_t aOffLane = (uint32_t)((m0w + (lane & 15)) * 80 + ((lane >> 4) << 4));
    uint32_t bRow = (uint32_t)(n0w + (lane & 7) + ((lane >> 4) << 3));
    uint32_t bHiBase = sb + DB_BHI + bRow * 272 + (((lane >> 3) & 1) << 4);
    uint32_t bLoBase = sb + DB_BLO + bRow * 272 + (((lane >> 3) & 1) << 4);

    float acc[4][4][4];
    #pragma unroll
    for (int a = 0; a < 4; a++)
        #pragma unroll
        for (int b = 0; b < 4; b++)
            #pragma unroll
            for (int r = 0; r < 4; r++) acc[a][b][r] = 0.f;

    for (int kq = 0; kq < 4; kq++) {
        int p = kq & 1;
        float4 rx[4];
        if (kq < 3) a_prefetch(rx, fused, X, h, offH, mbase, (kq+1)*32, t);

        uint32_t aHi = sb + DB_A + (uint32_t)(p*20480) + aOffLane;
        uint32_t aLo = aHi + 10240;
        #pragma unroll
        for (int ks = 0; ks < 2; ks++) {
            uint32_t koffA = (uint32_t)(ks * 32);
            uint32_t koffB = (uint32_t)(kq * 64 + ks * 32);
            uint32_t bh0[4], bl0[4], bh1[4], bl1[4];
            ldsm4(bh0, bHiBase + koffB);
            ldsm4(bh1, bHiBase + 16*272 + koffB);
            ldsm4(bl0, bLoBase + koffB);
            ldsm4(bl1, bLoBase + 16*272 + koffB);
            #pragma unroll
            for (int a = 0; a < 4; a++) {
                uint32_t ahi[4], alo[4];
                ldsm4(ahi, aHi + (uint32_t)(a*16*80) + koffA);
                ldsm4(alo, aLo + (uint32_t)(a*16*80) + koffA);
                // n-octet 0 (bp0,bb0) -> acc[a][0]
                mma_bf16(acc[a][0], ahi, bh0[0], bh0[1]);
                mma_bf16(acc[a][0], alo, bh0[0], bh0[1]);
                mma_bf16(acc[a][0], ahi, bl0[0], bl0[1]);
                // n-octet 1 (bp0,bb1) -> acc[a][1]
                mma_bf16(acc[a][1], ahi, bh0[2], bh0[3]);
                mma_bf16(acc[a][1], alo, bh0[2], bh0[3]);
                mma_bf16(acc[a][1], ahi, bl0[2], bl0[3]);
                // n-octet 2 (bp1,bb0) -> acc[a][2]
                mma_bf16(acc[a][2], ahi, bh1[0], bh1[1]);
                mma_bf16(acc[a][2], alo, bh1[0], bh1[1]);
                mma_bf16(acc[a][2], ahi, bl1[0], bl1[1]);
                // n-octet 3 (bp1,bb1) -> acc[a][3]
                mma_bf16(acc[a][3], ahi, bh1[2], bh1[3]);
                mma_bf16(acc[a][3], alo, bh1[2], bh1[3]);
                mma_bf16(acc[a][3], ahi, bl1[2], bl1[3]);
            }
        }
        if (kq < 3) {
            char* nb = smem + DB_A + (1 - p) * 20480;
            a_convert(rx, fused, center, offC, nb, nb + 10240, sa, sd, (kq+1)*32, t);
        }
        __syncthreads();
    }

    // epilogue: store Y + BN partials
    float ls[4][2], lq[4][2];
    #pragma unroll
    for (int b = 0; b < 4; b++) { ls[b][0]=0.f; ls[b][1]=0.f; lq[b][0]=0.f; lq[b][1]=0.f; }
    #pragma unroll
    for (int a = 0; a < 4; a++) {
        #pragma unroll
        for (int hf = 0; hf < 2; hf++) {
            int row = m0w + 16*a + g + 8*hf;
            float* yr = Y + (mbase + row)*CO + n0w + 2*q;
            #pragma unroll
            for (int b = 0; b < 4; b++) {
                float c0 = acc[a][b][2*hf], c1 = acc[a][b][2*hf + 1];
                *reinterpret_cast<float2*>(yr + 8*b) = make_float2(c0, c1);
                ls[b][0] += c0; ls[b][1] += c1;
                lq[b][0] = fmaf(c0, c0, lq[b][0]);
                lq[b][1] = fmaf(c1, c1, lq[b][1]);
            }
        }
    }
    #pragma unroll
    for (int b = 0; b < 4; b++) {
        #pragma unroll
        for (int p2 = 0; p2 < 2; p2++) {
            #pragma unroll
            for (int off = 4; off < 32; off <<= 1) {
                ls[b][p2] += __shfl_xor_sync(0xffffffffu, ls[b][p2], off);
                lq[b][p2] += __shfl_xor_sync(0xffffffffu, lq[b][p2], off);
            }
        }
    }
    float* redS = (float*)(smem + DB_A);          // overlay (A bufs dead)
    float* redQ = (float*)(smem + DB_A + 4096);
    if (lane < 4) {
        #pragma unroll
        for (int b = 0; b < 4; b++) {
            #pragma unroll
            for (int p2 = 0; p2 < 2; p2++) {
                int cs = 8*b + 2*lane + p2;
                redS[wid*32 + cs] = ls[b][p2];
                redQ[wid*32 + cs] = lq[b][p2];
            }
        }
    }
    __syncthreads();
    if (t < 128) {
        int wnc = t >> 5, cw = t & 31;
        float Sv = redS[wnc*32 + cw] + redS[(wnc+4)*32 + cw];
        float Qv = redQ[wnc*32 + cw] + redQ[(wnc+4)*32 + cw];
        part[blockIdx.x*256 + t]       = Sv;
        part[blockIdx.x*256 + 128 + t] = Qv;
    }
}

__global__ __launch_bounds__(256, 2)
void gemm1_mma(const float* __restrict__ center, const float* __restrict__ h,
               const int* __restrict__ idx,
               const __nv_bfloat16* __restrict__ Whi, const __nv_bfloat16* __restrict__ Wlo,
               const float* __restrict__ coef, float* __restrict__ Y,
               float* __restrict__ part) {
    gemm_mma_core(true, nullptr, center, h, idx, Whi, Wlo, coef, Y, part);
}

__global__ __launch_bounds__(256, 2)
void gemm2_mma(const float* __restrict__ X,
               const __nv_bfloat16* __restrict__ Whi, const __nv_bfloat16* __restrict__ Wlo,
               const float* __restrict__ coef, float* __restrict__ Y,
               float* __restrict__ part) {
    gemm_mma_core(false, X, nullptr, nullptr, nullptr, Whi, Wlo, coef, Y, part);
}

// ------------------------- final: mean_k relu(bn2) + bn_sc + relu, transpose -
__global__ void final_kernel(const float* __restrict__ x2, const float* __restrict__ sc,
                             const float* __restrict__ coef2, const float* __restrict__ coefsc,
                             float* __restrict__ out) {
    __shared__ float tile[32*129];
    int t = threadIdx.x;
    int blk = blockIdx.x;
    int b = blk >> 5;
    int n0 = (blk & 31) << 5;
    #pragma unroll
    for (int i = 0; i < 16; i++) {
        int idx = t + 256*i;
        int o = idx & 127, nn = idx >> 7;
        int bn = b*NN + n0 + nn;
        float a2 = coef2[o], d2 = coef2[128 + o];
        const float* xr = x2 + (size_t)bn * KNN * CO + o;
        float s = 0.f;
        #pragma unroll
        for (int k = 0; k < KNN; k++)
            s += fmaxf(fmaf(a2, xr[k*CO], d2), 0.f);
        float scv = sc[bn*CO + o];
        float as = coefsc[o], ds = coefsc[128 + o];
        tile[nn*129 + o] = fmaxf(fmaf(as, scv, ds) + s * (1.f/16.f), 0.f);
    }
    __syncthreads();
    #pragma unroll
    for (int i = 0; i < 16; i++) {
        int idx = t + 256*i;
        int nn = idx & 31, o = idx >> 5;
        out[(size_t)b*CO*NN + o*NN + n0 + nn] = tile[nn*129 + o];
    }
}

// ------------------------- host launcher -------------------------------------
extern "C" void kernel_launch(void* const* d_in, const int* in_sizes, int n_in,
                              void* d_out, int out_size) {
    const float* points   = (const float*)d_in[0];
    const float* features = (const float*)d_in[1];
    const float* W0  = (const float*)d_in[2];
    const float* g0  = (const float*)d_in[3];
    const float* b0  = (const float*)d_in[4];
    const float* W1  = (const float*)d_in[5];
    const float* g1  = (const float*)d_in[6];
    const float* b1  = (const float*)d_in[7];
    const float* W2  = (const float*)d_in[8];
    const float* g2  = (const float*)d_in[9];
    const float* b2  = (const float*)d_in[10];
    const float* Wsc = (const float*)d_in[11];
    const float* gsc = (const float*)d_in[12];
    const float* bsc = (const float*)d_in[13];
    float* out = (float*)d_out;

    void *p_idx, *p_center, *p_h, *p_sc, *p_x1, *p_x2, *p_part, *p_partsc, *p_coef;
    void *p_w1hi, *p_w1lo, *p_w2hi, *p_w2lo;
    cudaGetSymbolAddress(&p_idx,    g_idx);
    cudaGetSymbolAddress(&p_center, g_center);
    cudaGetSymbolAddress(&p_h,      g_h);
    cudaGetSymbolAddress(&p_sc,     g_sc);
    cudaGetSymbolAddress(&p_x1,     g_x1);
    cudaGetSymbolAddress(&p_x2,     g_x2);
    cudaGetSymbolAddress(&p_part,   g_part);
    cudaGetSymbolAddress(&p_partsc, g_partsc);
    cudaGetSymbolAddress(&p_coef,   g_coef);
    cudaGetSymbolAddress(&p_w1hi,   g_w1hi);
    cudaGetSymbolAddress(&p_w1lo,   g_w1lo);
    cudaGetSymbolAddress(&p_w2hi,   g_w2hi);
    cudaGetSymbolAddress(&p_w2lo,   g_w2lo);

    int*   idx    = (int*)p_idx;
    float* center = (float*)p_center;
    float* h      = (float*)p_h;
    float* sc     = (float*)p_sc;
    float* x1     = (float*)p_x1;
    float* x2     = (float*)p_x2;
    float* part   = (float*)p_part;
    float* partsc = (float*)p_partsc;
    float* coef0  = (float*)p_coef;
    float* coef1  = coef0 + 256;
    float* coef2  = coef0 + 512;
    float* coef3  = coef0 + 768;
    __nv_bfloat16* w1hi = (__nv_bfloat16*)p_w1hi;
    __nv_bfloat16* w1lo = (__nv_bfloat16*)p_w1lo;
    __nv_bfloat16* w2hi = (__nv_bfloat16*)p_w2hi;
    __nv_bfloat16* w2lo = (__nv_bfloat16*)p_w2lo;

    const float invM  = 1.f / (float)ROWS;
    const float invMs = 1.f / (float)BNROWS;

    cudaFuncSetAttribute(gemm1_mma, cudaFuncAttributeMaxDynamicSharedMemorySize, DB_TOTAL);
    cudaFuncSetAttribute(gemm2_mma, cudaFuncAttributeMaxDynamicSharedMemorySize, DB_TOTAL);

    whilo_kernel<<<64, 256>>>(W1, W2, w1hi, w1lo, w2hi, w2lo);
    knn_kernel<<<GEMM_BLOCKS, 256>>>(points, idx);
    feat_kernel<<<BNROWS/16, 128>>>(features, W0, Wsc, center, h, sc);
    buildstats_kernel<<<GEMM_BLOCKS, 256>>>(center, h, idx, part);
    colpart_kernel<<<256, 256>>>(sc, partsc);
    stats_kernel<<<128, 256>>>(part, GEMM_BLOCKS, g0, b0, coef0, invM);
    stats_kernel<<<128, 256>>>(partsc, 256, gsc, bsc, coef3, invMs);
    gemm1_mma<<<GEMM_BLOCKS, 256, DB_TOTAL>>>(center, h, idx, w1hi, w1lo, coef0, x1, part);
    stats_kernel<<<128, 256>>>(part, GEMM_BLOCKS, g1, b1, coef1, invM);
    gemm2_mma<<<GEMM_BLOCKS, 256, DB_TOTAL>>>(x1, w2hi, w2lo, coef1, x2, part);
    stats_kernel<<<128, 256>>>(part, GEMM_BLOCKS, g2, b2, coef2, invM);
    final_kernel<<<1024, 256>>>(x2, sc, coef2, coef3, out);
}

// round 9
// speedup vs baseline: 4.4046x; 1.0960x over previous
#include <cuda_runtime.h>
#include <cuda_bf16.h>
#include <cuda_fp16.h>
#include <math.h>
#include <stdint.h>

// Problem constants
#define BB   32
#define NN   1024
#define CIN  64
#define CO   128
#define KNN  16
#define BNROWS (BB*NN)          // 32768
#define ROWS   (BNROWS*KNN)     // 524288
#define GEMM_BLOCKS (ROWS/128)  // 4096
#define EPSV 1e-5f

// ------------------------- device scratch (static, no allocs) ----------------
static __device__ int   g_idx[ROWS];                  // 2 MB
static __device__ float g_center[BNROWS*CO];          // 16 MB
static __device__ float g_h[BNROWS*CO];               // 16 MB
static __device__ float g_sc[BNROWS*CO];              // 16 MB
static __device__ float g_x1[(size_t)ROWS*CO];        // 268 MB (layer-1 out)
static __device__ float g_x2[(size_t)ROWS*CO];        // 268 MB (layer-2 out)
static __device__ float g_part[GEMM_BLOCKS*256];      // 4 MB
static __device__ float g_partsc[256*256];            // 256 KB
static __device__ float g_coef[4*256];                // (a[128],d[128]) x4
static __device__ __half g_w1h[CO*CO];                // fp16-rounded weights
static __device__ __half g_w2h[CO*CO];

// ------------------------- PTX helpers ---------------------------------------
__device__ __forceinline__ uint32_t smem_u32(const void* p) {
    uint32_t a;
    asm("{ .reg .u64 t; cvta.to.shared.u64 t, %1; cvt.u32.u64 %0, t; }" : "=r"(a) : "l"(p));
    return a;
}
__device__ __forceinline__ void ldsm4(uint32_t* r, uint32_t addr) {
    asm volatile("ldmatrix.sync.aligned.m8n8.x4.shared.b16 {%0,%1,%2,%3}, [%4];"
        : "=r"(r[0]), "=r"(r[1]), "=r"(r[2]), "=r"(r[3]) : "r"(addr));
}
__device__ __forceinline__ void mma_f16(float* c, const uint32_t* a, uint32_t b0, uint32_t b1) {
    asm volatile("mma.sync.aligned.m16n8k16.row.col.f32.f16.f16.f32 "
        "{%0,%1,%2,%3}, {%4,%5,%6,%7}, {%8,%9}, {%0,%1,%2,%3};"
        : "+f"(c[0]), "+f"(c[1]), "+f"(c[2]), "+f"(c[3])
        : "r"(a[0]), "r"(a[1]), "r"(a[2]), "r"(a[3]), "r"(b0), "r"(b1));
}
__device__ __forceinline__ uint32_t packh2(__half a, __half b) {
    return (uint32_t)__half_as_ushort(a) | ((uint32_t)__half_as_ushort(b) << 16);
}

// ------------------------- dynamic smem layout (bytes) ------------------------
// B hi (full K, resident): rows stride 136 halves = 272 B -> ldmatrix conflict-free
#define DB_BH    0          // 128*272 = 34816
#define DB_A     34816      // 2 bufs x (hi 10240 + lo 10240) = 40960 -> 75776
#define DB_SA    75776      // 512
#define DB_SD    76288      // 512
#define DB_OFFC  76800      // 512
#define DB_OFFH  77312      // 512
#define DB_TOTAL 77824

// ------------------------- 0) W fp16 precompute -------------------------------
__global__ void whalf_kernel(const float* __restrict__ W1, const float* __restrict__ W2,
                             __half* __restrict__ w1h, __half* __restrict__ w2h) {
    int i = blockIdx.x * 256 + threadIdx.x;   // 16384
    w1h[i] = __float2half_rn(W1[i]);
    w2h[i] = __float2half_rn(W2[i]);
}

// ------------------------- 1) kNN: warp per query, register-resident ---------
__global__ __launch_bounds__(256)
void knn_kernel(const float* __restrict__ pts, int* __restrict__ idxout) {
    __shared__ float sx[NN], sy[NN], sz[NN], sxx[NN];
    int t = threadIdx.x;
    int wid = t >> 5, lane = t & 31;
    int blk = blockIdx.x;
    int b = blk >> 7;
    int n = ((blk & 127) << 3) + wid;
    const float* P = pts + (size_t)b * 3 * NN;
    for (int m = t; m < NN; m += 256) {
        float x = P[m], y = P[NN + m], z = P[2*NN + m];
        sx[m] = x; sy[m] = y; sz[m] = z;
        sxx[m] = x*x + y*y + z*z;
    }
    __syncthreads();
    float qx = sx[n], qy = sy[n], qz = sz[n], qxx = sxx[n];
    float d[32];
    #pragma unroll
    for (int j = 0; j < 32; j++) {
        int m = j*32 + lane;
        float dd = 2.f*(qx*sx[m] + qy*sy[m] + qz*sz[m]) - qxx - sxx[m];
        d[j] = (m == n) ? -INFINITY : dd;
    }
    int* op = idxout + ((size_t)b*NN + n) * KNN;
    unsigned alive = 0xffffffffu;
    for (int r = 0; r < KNN; r++) {
        float bv = -INFINITY; int bj = 0;
        #pragma unroll
        for (int j = 0; j < 32; j++) {
            float dj = (alive & (1u << j)) ? d[j] : -INFINITY;
            if (dj > bv) { bv = dj; bj = j; }
        }
        int bi = bj*32 + lane;
        #pragma unroll
        for (int s = 16; s > 0; s >>= 1) {
            float ov = __shfl_down_sync(0xffffffffu, bv, s);
            int   oi = __shfl_down_sync(0xffffffffu, bi, s);
            if (ov > bv || (ov == bv && oi < bi)) { bv = ov; bi = oi; }
        }
        bi = __shfl_sync(0xffffffffu, bi, 0);
        if (lane == 0) op[r] = bi;
        if ((bi & 31) == lane) alive &= ~(1u << (bi >> 5));
    }
}

// ------------------------- 2) per-point GEMVs --------------------------------
__global__ void feat_kernel(const float* __restrict__ f,
                            const float* __restrict__ W0,
                            const float* __restrict__ Wsc,
                            float* __restrict__ center,
                            float* __restrict__ h,
                            float* __restrict__ sc) {
    __shared__ float fs[CIN][16];
    int base = blockIdx.x * 16;
    int b = base >> 10, n0 = base & 1023;
    int t = threadIdx.x;
    #pragma unroll
    for (int i = 0; i < 8; i++) {
        int idx = t + 128*i;
        int c = idx >> 4, j = idx & 15;
        fs[c][j] = f[(size_t)b*CIN*NN + c*NN + n0 + j];
    }
    __syncthreads();
    int o = t;
    float ctr[16], hh[16], ss[16];
    #pragma unroll
    for (int j = 0; j < 16; j++) { ctr[j]=0.f; hh[j]=0.f; ss[j]=0.f; }
    for (int c = 0; c < CIN; c++) {
        float w0a = W0[o*128 + c];
        float w0b = W0[o*128 + 64 + c];
        float ws  = Wsc[o*64 + c];
        float wc  = w0a - w0b;
        const float* fr = fs[c];
        #pragma unroll
        for (int j = 0; j < 16; j++) {
            float fv = fr[j];
            ctr[j] = fmaf(wc,  fv, ctr[j]);
            hh[j]  = fmaf(w0b, fv, hh[j]);
            ss[j]  = fmaf(ws,  fv, ss[j]);
        }
    }
    #pragma unroll
    for (int j = 0; j < 16; j++) {
        int row = base + j;
        center[row*CO + o] = ctr[j];
        h[row*CO + o]      = hh[j];
        sc[row*CO + o]     = ss[j];
    }
}

// ------------------------- 3) layer-0 stats only -----------------------------
__global__ void buildstats_kernel(const float* __restrict__ center,
                                  const float* __restrict__ h,
                                  const int* __restrict__ idx,
                                  float* __restrict__ part) {
    __shared__ float red[8][132];
    int t = threadIdx.x;
    int oq = (t & 31) << 2;
    int strip = t >> 5;
    int bn = blockIdx.x * 8 + strip;
    int b = bn >> 10;
    float4 c4 = *reinterpret_cast<const float4*>(&center[bn*CO + oq]);
    const int* ip = idx + bn*KNN;
    float s0=0,s1=0,s2=0,s3=0, q0=0,q1=0,q2=0,q3=0;
    #pragma unroll
    for (int k = 0; k < KNN; k++) {
        int gi = ip[k];
        float4 h4 = *reinterpret_cast<const float4*>(&h[(b*NN + gi)*CO + oq]);
        float vx = c4.x + h4.x, vy = c4.y + h4.y, vz = c4.z + h4.z, vw = c4.w + h4.w;
        s0 += vx; s1 += vy; s2 += vz; s3 += vw;
        q0 = fmaf(vx,vx,q0); q1 = fmaf(vy,vy,q1); q2 = fmaf(vz,vz,q2); q3 = fmaf(vw,vw,q3);
    }
    red[strip][oq+0]=s0; red[strip][oq+1]=s1; red[strip][oq+2]=s2; red[strip][oq+3]=s3;
    __syncthreads();
    if (t < 128) {
        float s = 0;
        #pragma unroll
        for (int q = 0; q < 8; q++) s += red[q][t];
        part[blockIdx.x*256 + t] = s;
    }
    __syncthreads();
    red[strip][oq+0]=q0; red[strip][oq+1]=q1; red[strip][oq+2]=q2; red[strip][oq+3]=q3;
    __syncthreads();
    if (t < 128) {
        float s = 0;
        #pragma unroll
        for (int q = 0; q < 8; q++) s += red[q][t];
        part[blockIdx.x*256 + 128 + t] = s;
    }
}

// ------------------------- 4) stats: partials -> (a, d) ----------------------
__global__ void stats_kernel(const float* __restrict__ part, int nparts,
                             const float* __restrict__ g, const float* __restrict__ bt,
                             float* __restrict__ coef, float invM) {
    __shared__ float ss[256], qq[256];
    int o = blockIdx.x, t = threadIdx.x;
    float s = 0.f, q = 0.f;
    for (int p = t; p < nparts; p += 256) {
        s += part[p*256 + o];
        q += part[p*256 + 128 + o];
    }
    ss[t] = s; qq[t] = q;
    __syncthreads();
    for (int st = 128; st > 0; st >>= 1) {
        if (t < st) { ss[t] += ss[t+st]; qq[t] += qq[t+st]; }
        __syncthreads();
    }
    if (t == 0) {
        float mean = ss[0] * invM;
        float var  = qq[0] * invM - mean*mean;
        float a = g[o] / sqrtf(var + EPSV);
        coef[o] = a;
        coef[128 + o] = bt[o] - mean * a;
    }
}

// coalesced partial-sum over sc (rows x 128), 128 rows per block
__global__ void colpart_kernel(const float* __restrict__ X, float* __restrict__ part) {
    __shared__ float sm0[2][128], sm1[2][128];
    int t = threadIdx.x;
    int o = t & 127, hf = t >> 7;
    int r0 = blockIdx.x * 128 + hf * 64;
    float s = 0.f, q = 0.f;
    for (int i = 0; i < 64; i++) {
        float v = X[(size_t)(r0 + i)*CO + o];
        s += v; q = fmaf(v, v, q);
    }
    sm0[hf][o] = s; sm1[hf][o] = q;
    __syncthreads();
    if (t < 128) {
        part[blockIdx.x*256 + t]       = sm0[0][t] + sm0[1][t];
        part[blockIdx.x*256 + 128 + t] = sm1[0][t] + sm1[1][t];
    }
}

// ------------------------- pipelined mma.sync fp16 2x GEMM -------------------
// 256 threads, tile 128m x 128n, K=128. W (fp16 hi, exact-A equivalent) smem-resident.
// A quarters (32 k) double-buffered: prefetch LDG -> mma -> cvt+STS.
__device__ __forceinline__ void a_prefetch(float4* rx, bool fused,
                                           const float* __restrict__ X,
                                           const float* __restrict__ h,
                                           const int* offH, size_t mbase, int cq, int t) {
    #pragma unroll
    for (int i = 0; i < 4; i++) {
        int e = t + 256*i;
        int c4 = e & 7, m = e >> 3;
        const float* src = fused ? (h + offH[m] + cq + c4*4)
                                 : (X + (mbase + m)*CO + cq + c4*4);
        rx[i] = *reinterpret_cast<const float4*>(src);
    }
}

__device__ __forceinline__ void a_convert(const float4* rx, bool fused,
                                          const float* __restrict__ center, const int* offC,
                                          char* bufHi, char* bufLo,
                                          const float* sa, const float* sd, int cq, int t) {
    #pragma unroll
    for (int i = 0; i < 4; i++) {
        int e = t + 256*i;
        int c4 = e & 7, m = e >> 3;
        int c0 = c4*4;
        float v0 = rx[i].x, v1 = rx[i].y, v2 = rx[i].z, v3 = rx[i].w;
        if (fused) {
            float4 cv = *reinterpret_cast<const float4*>(center + offC[m] + cq + c0);
            v0 += cv.x; v1 += cv.y; v2 += cv.z; v3 += cv.w;
        }
        v0 = fmaxf(fmaf(sa[cq+c0+0], v0, sd[cq+c0+0]), 0.f);
        v1 = fmaxf(fmaf(sa[cq+c0+1], v1, sd[cq+c0+1]), 0.f);
        v2 = fmaxf(fmaf(sa[cq+c0+2], v2, sd[cq+c0+2]), 0.f);
        v3 = fmaxf(fmaf(sa[cq+c0+3], v3, sd[cq+c0+3]), 0.f);
        __half h0 = __float2half_rn(v0), h1 = __float2half_rn(v1);
        __half h2 = __float2half_rn(v2), h3 = __float2half_rn(v3);
        __half l0 = __float2half_rn(v0 - __half2float(h0));
        __half l1 = __float2half_rn(v1 - __half2float(h1));
        __half l2 = __float2half_rn(v2 - __half2float(h2));
        __half l3 = __float2half_rn(v3 - __half2float(h3));
        *reinterpret_cast<uint2*>(bufHi + m*80 + c0*2) =
            make_uint2(packh2(h0, h1), packh2(h2, h3));
        *reinterpret_cast<uint2*>(bufLo + m*80 + c0*2) =
            make_uint2(packh2(l0, l1), packh2(l2, l3));
    }
}

__device__ __forceinline__ void gemm_mma_core(
    bool fused, const float* __restrict__ X,
    const float* __restrict__ center, const float* __restrict__ h,
    const int* __restrict__ idx,
    const __half* __restrict__ Wh,
    const float* __restrict__ coef,
    float* __restrict__ Y, float* __restrict__ part)
{
    extern __shared__ char smem[];
    int t = threadIdx.x;
    int wid = t >> 5, lane = t & 31;
    int wm = wid >> 2, wn = wid & 3;       // warp grid 2m x 4n
    int m0w = wm * 64, n0w = wn * 32;
    int g = lane >> 2, q = lane & 3;
    size_t mbase = (size_t)blockIdx.x * 128;

    float* sa = (float*)(smem + DB_SA);
    float* sd = (float*)(smem + DB_SD);
    int* offC = (int*)(smem + DB_OFFC);
    int* offH = (int*)(smem + DB_OFFH);

    if (t < 128) {
        sa[t] = coef[t];
        sd[t] = coef[128 + t];
        if (fused) {
            int G = (int)mbase + t;
            int bn = G >> 4;
            int gi = idx[G];
            offC[t] = bn * CO;
            offH[t] = ((bn >> 10) * NN + gi) * CO;
        }
    }
    // load W hi into smem, rows stride 136 halves (68 u32)
    {
        const uint32_t* wh = reinterpret_cast<const uint32_t*>(Wh);
        uint32_t* bh = reinterpret_cast<uint32_t*>(smem + DB_BH);
        #pragma unroll
        for (int i = 0; i < 32; i++) {
            int e = t + 256*i;          // 8192 u32
            int c2 = e & 63, o = e >> 6;
            bh[o*68 + c2] = wh[e];
        }
    }
    __syncthreads();

    // build quarter 0 into buf 0
    {
        float4 rx[4];
        a_prefetch(rx, fused, X, h, offH, mbase, 0, t);
        a_convert(rx, fused, center, offC, smem + DB_A, smem + DB_A + 10240, sa, sd, 0, t);
    }
    __syncthreads();

    uint32_t sb = smem_u32(smem);
    uint32_t aOffLane = (uint32_t)((m0w + (lane & 15)) * 80 + ((lane >> 4) << 4));
    uint32_t bRow = (uint32_t)(n0w + (lane & 7) + ((lane >> 4) << 3));
    uint32_t bHiBase = sb + DB_BH + bRow * 272 + (((lane >> 3) & 1) << 4);

    float acc[4][4][4];
    #pragma unroll
    for (int a = 0; a < 4; a++)
        #pragma unroll
        for (int b = 0; b < 4; b++)
            #pragma unroll
            for (int r = 0; r < 4; r++) acc[a][b][r] = 0.f;

    for (int kq = 0; kq < 4; kq++) {
        int p = kq & 1;
        float4 rx[4];
        if (kq < 3) a_prefetch(rx, fused, X, h, offH, mbase, (kq+1)*32, t);

        uint32_t aHi = sb + DB_A + (uint32_t)(p*20480) + aOffLane;
        uint32_t aLo = aHi + 10240;
        #pragma unroll
        for (int ks = 0; ks < 2; ks++) {
            uint32_t koffA = (uint32_t)(ks * 32);
            uint32_t koffB = (uint32_t)(kq * 64 + ks * 32);
            uint32_t bh0[4], bh1[4];
            ldsm4(bh0, bHiBase + koffB);
            ldsm4(bh1, bHiBase + 16*272 + koffB);
            #pragma unroll
            for (int a = 0; a < 4; a++) {
                uint32_t ahi[4], alo[4];
                ldsm4(ahi, aHi + (uint32_t)(a*16*80) + koffA);
                ldsm4(alo, aLo + (uint32_t)(a*16*80) + koffA);
                mma_f16(acc[a][0], ahi, bh0[0], bh0[1]);
                mma_f16(acc[a][0], alo, bh0[0], bh0[1]);
                mma_f16(acc[a][1], ahi, bh0[2], bh0[3]);
                mma_f16(acc[a][1], alo, bh0[2], bh0[3]);
                mma_f16(acc[a][2], ahi, bh1[0], bh1[1]);
                mma_f16(acc[a][2], alo, bh1[0], bh1[1]);
                mma_f16(acc[a][3], ahi, bh1[2], bh1[3]);
                mma_f16(acc[a][3], alo, bh1[2], bh1[3]);
            }
        }
        if (kq < 3) {
            char* nb = smem + DB_A + (1 - p) * 20480;
            a_convert(rx, fused, center, offC, nb, nb + 10240, sa, sd, (kq+1)*32, t);
        }
        __syncthreads();
    }

    // epilogue: store Y + BN partials
    float ls[4][2], lq[4][2];
    #pragma unroll
    for (int b = 0; b < 4; b++) { ls[b][0]=0.f; ls[b][1]=0.f; lq[b][0]=0.f; lq[b][1]=0.f; }
    #pragma unroll
    for (int a = 0; a < 4; a++) {
        #pragma unroll
        for (int hf = 0; hf < 2; hf++) {
            int row = m0w + 16*a + g + 8*hf;
            float* yr = Y + (mbase + row)*CO + n0w + 2*q;
            #pragma unroll
            for (int b = 0; b < 4; b++) {
                float c0 = acc[a][b][2*hf], c1 = acc[a][b][2*hf + 1];
                *reinterpret_cast<float2*>(yr + 8*b) = make_float2(c0, c1);
                ls[b][0] += c0; ls[b][1] += c1;
                lq[b][0] = fmaf(c0, c0, lq[b][0]);
                lq[b][1] = fmaf(c1, c1, lq[b][1]);
            }
        }
    }
    #pragma unroll
    for (int b = 0; b < 4; b++) {
        #pragma unroll
        for (int p2 = 0; p2 < 2; p2++) {
            #pragma unroll
            for (int off = 4; off < 32; off <<= 1) {
                ls[b][p2] += __shfl_xor_sync(0xffffffffu, ls[b][p2], off);
                lq[b][p2] += __shfl_xor_sync(0xffffffffu, lq[b][p2], off);
            }
        }
    }
    float* redS = (float*)(smem + DB_A);          // overlay (A bufs dead)
    float* redQ = (float*)(smem + DB_A + 4096);
    if (lane < 4) {
        #pragma unroll
        for (int b = 0; b < 4; b++) {
            #pragma unroll
            for (int p2 = 0; p2 < 2; p2++) {
                int cs = 8*b + 2*lane + p2;
                redS[wid*32 + cs] = ls[b][p2];
                redQ[wid*32 + cs] = lq[b][p2];
            }
        }
    }
    __syncthreads();
    if (t < 128) {
        int wnc = t >> 5, cw = t & 31;
        float Sv = redS[wnc*32 + cw] + redS[(wnc+4)*32 + cw];
        float Qv = redQ[wnc*32 + cw] + redQ[(wnc+4)*32 + cw];
        part[blockIdx.x*256 + t]       = Sv;
        part[blockIdx.x*256 + 128 + t] = Qv;
    }
}

__global__ __launch_bounds__(256, 2)
void gemm1_mma(const float* __restrict__ center, const float* __restrict__ h,
               const int* __restrict__ idx,
               const __half* __restrict__ Wh,
               const float* __restrict__ coef, float* __restrict__ Y,
               float* __restrict__ part) {
    gemm_mma_core(true, nullptr, center, h, idx, Wh, coef, Y, part);
}

__global__ __launch_bounds__(256, 2)
void gemm2_mma(const float* __restrict__ X,
               const __half* __restrict__ Wh,
               const float* __restrict__ coef, float* __restrict__ Y,
               float* __restrict__ part) {
    gemm_mma_core(false, X, nullptr, nullptr, nullptr, Wh, coef, Y, part);
}

// ------------------------- final: mean_k relu(bn2) + bn_sc + relu, transpose -
// grid 4096 = 32 b x 128 groups of 8 n-rows
__global__ void final_kernel(const float* __restrict__ x2, const float* __restrict__ sc,
                             const float* __restrict__ coef2, const float* __restrict__ coefsc,
                             float* __restrict__ out) {
    __shared__ float tile[8*129];
    int t = threadIdx.x;
    int blk = blockIdx.x;
    int b = blk >> 7;
    int n0 = (blk & 127) << 3;
    #pragma unroll
    for (int i = 0; i < 4; i++) {
        int idx = t + 256*i;
        int o = idx & 127, nn = idx >> 7;
        int bn = b*NN + n0 + nn;
        float a2 = coef2[o], d2 = coef2[128 + o];
        const float* xr = x2 + (size_t)bn * KNN * CO + o;
        float s = 0.f;
        #pragma unroll
        for (int k = 0; k < KNN; k++)
            s += fmaxf(fmaf(a2, xr[k*CO], d2), 0.f);
        float scv = sc[bn*CO + o];
        float as = coefsc[o], ds = coefsc[128 + o];
        tile[nn*129 + o] = fmaxf(fmaf(as, scv, ds) + s * (1.f/16.f), 0.f);
    }
    __syncthreads();
    #pragma unroll
    for (int i = 0; i < 4; i++) {
        int idx = t + 256*i;
        int nn = idx & 7, o = idx >> 3;
        out[(size_t)b*CO*NN + o*NN + n0 + nn] = tile[nn*129 + o];
    }
}

// ------------------------- host launcher -------------------------------------
extern "C" void kernel_launch(void* const* d_in, const int* in_sizes, int n_in,
                              void* d_out, int out_size) {
    const float* points   = (const float*)d_in[0];
    const float* features = (const float*)d_in[1];
    const float* W0  = (const float*)d_in[2];
    const float* g0  = (const float*)d_in[3];
    const float* b0  = (const float*)d_in[4];
    const float* W1  = (const float*)d_in[5];
    const float* g1  = (const float*)d_in[6];
    const float* b1  = (const float*)d_in[7];
    const float* W2  = (const float*)d_in[8];
    const float* g2  = (const float*)d_in[9];
    const float* b2  = (const float*)d_in[10];
    const float* Wsc = (const float*)d_in[11];
    const float* gsc = (const float*)d_in[12];
    const float* bsc = (const float*)d_in[13];
    float* out = (float*)d_out;

    void *p_idx, *p_center, *p_h, *p_sc, *p_x1, *p_x2, *p_part, *p_partsc, *p_coef;
    void *p_w1h, *p_w2h;
    cudaGetSymbolAddress(&p_idx,    g_idx);
    cudaGetSymbolAddress(&p_center, g_center);
    cudaGetSymbolAddress(&p_h,      g_h);
    cudaGetSymbolAddress(&p_sc,     g_sc);
    cudaGetSymbolAddress(&p_x1,     g_x1);
    cudaGetSymbolAddress(&p_x2,     g_x2);
    cudaGetSymbolAddress(&p_part,   g_part);
    cudaGetSymbolAddress(&p_partsc, g_partsc);
    cudaGetSymbolAddress(&p_coef,   g_coef);
    cudaGetSymbolAddress(&p_w1h,    g_w1h);
    cudaGetSymbolAddress(&p_w2h,    g_w2h);

    int*   idx    = (int*)p_idx;
    float* center = (float*)p_center;
    float* h      = (float*)p_h;
    float* sc     = (float*)p_sc;
    float* x1     = (float*)p_x1;
    float* x2     = (float*)p_x2;
    float* part   = (float*)p_part;
    float* partsc = (float*)p_partsc;
    float* coef0  = (float*)p_coef;
    float* coef1  = coef0 + 256;
    float* coef2  = coef0 + 512;
    float* coef3  = coef0 + 768;
    __half* w1h = (__half*)p_w1h;
    __half* w2h = (__half*)p_w2h;

    const float invM  = 1.f / (float)ROWS;
    const float invMs = 1.f / (float)BNROWS;

    cudaFuncSetAttribute(gemm1_mma, cudaFuncAttributeMaxDynamicSharedMemorySize, DB_TOTAL);
    cudaFuncSetAttribute(gemm2_mma, cudaFuncAttributeMaxDynamicSharedMemorySize, DB_TOTAL);

    whalf_kernel<<<64, 256>>>(W1, W2, w1h, w2h);
    knn_kernel<<<GEMM_BLOCKS, 256>>>(points, idx);
    feat_kernel<<<BNROWS/16, 128>>>(features, W0, Wsc, center, h, sc);
    buildstats_kernel<<<GEMM_BLOCKS, 256>>>(center, h, idx, part);
    colpart_kernel<<<256, 256>>>(sc, partsc);
    stats_kernel<<<128, 256>>>(part, GEMM_BLOCKS, g0, b0, coef0, invM);
    stats_kernel<<<128, 256>>>(partsc, 256, gsc, bsc, coef3, invMs);
    gemm1_mma<<<GEMM_BLOCKS, 256, DB_TOTAL>>>(center, h, idx, w1h, coef0, x1, part);
    stats_kernel<<<128, 256>>>(part, GEMM_BLOCKS, g1, b1, coef1, invM);
    gemm2_mma<<<GEMM_BLOCKS, 256, DB_TOTAL>>>(x1, w2h, coef1, x2, part);
    stats_kernel<<<128, 256>>>(part, GEMM_BLOCKS, g2, b2, coef2, invM);
    final_kernel<<<4096, 256>>>(x2, sc, coef2, coef3, out);
}

// round 11
// speedup vs baseline: 4.8107x; 1.0922x over previous
#include <cuda_runtime.h>
#include <cuda_bf16.h>
#include <cuda_fp16.h>
#include <math.h>
#include <stdint.h>

// Problem constants
#define BB   32
#define NN   1024
#define CIN  64
#define CO   128
#define KNN  16
#define BNROWS (BB*NN)          // 32768
#define ROWS   (BNROWS*KNN)     // 524288
#define GEMM_BLOCKS (ROWS/128)  // 4096
#define EPSV 1e-5f

// ------------------------- device scratch (static, no allocs) ----------------
static __device__ int    g_idx[ROWS];                 // 2 MB
static __device__ float  g_center[BNROWS*CO];         // 16 MB
static __device__ float  g_h[BNROWS*CO];              // 16 MB
static __device__ float  g_sc[BNROWS*CO];             // 16 MB
static __device__ __half g_x1[(size_t)ROWS*CO];       // 134 MB (layer-1 out, fp16)
static __device__ __half g_x2[(size_t)ROWS*CO];       // 134 MB (layer-2 out, fp16)
static __device__ float  g_part[GEMM_BLOCKS*256];     // 4 MB
static __device__ float  g_partsc[256*256];           // 256 KB
static __device__ float  g_coef[4*256];               // (a[128],d[128]) x4
static __device__ __half g_w1h[CO*CO];                // fp16-rounded weights
static __device__ __half g_w2h[CO*CO];

// ------------------------- PTX helpers ---------------------------------------
__device__ __forceinline__ uint32_t smem_u32(const void* p) {
    uint32_t a;
    asm("{ .reg .u64 t; cvta.to.shared.u64 t, %1; cvt.u32.u64 %0, t; }" : "=r"(a) : "l"(p));
    return a;
}
__device__ __forceinline__ void ldsm4(uint32_t* r, uint32_t addr) {
    asm volatile("ldmatrix.sync.aligned.m8n8.x4.shared.b16 {%0,%1,%2,%3}, [%4];"
        : "=r"(r[0]), "=r"(r[1]), "=r"(r[2]), "=r"(r[3]) : "r"(addr));
}
__device__ __forceinline__ void mma_f16(float* c, const uint32_t* a, uint32_t b0, uint32_t b1) {
    asm volatile("mma.sync.aligned.m16n8k16.row.col.f32.f16.f16.f32 "
        "{%0,%1,%2,%3}, {%4,%5,%6,%7}, {%8,%9}, {%0,%1,%2,%3};"
        : "+f"(c[0]), "+f"(c[1]), "+f"(c[2]), "+f"(c[3])
        : "r"(a[0]), "r"(a[1]), "r"(a[2]), "r"(a[3]), "r"(b0), "r"(b1));
}
__device__ __forceinline__ uint32_t packh2(__half a, __half b) {
    return (uint32_t)__half_as_ushort(a) | ((uint32_t)__half_as_ushort(b) << 16);
}

// ------------------------- dynamic smem layout (bytes) ------------------------
// B hi (full K, resident): rows stride 136 halves = 272 B -> ldmatrix conflict-free
// A: 2 bufs x 10240 (fp16 only, rows stride 80 B)
#define DB_BH    0          // 34816
#define DB_A     34816      // 2 x 10240 -> 55296
#define DB_SA    55296      // 512
#define DB_SD    55808      // 512
#define DB_OFFC  56320      // 512
#define DB_OFFH  56832      // 512
#define DB_TOTAL 57344

// ------------------------- 0) W fp16 precompute -------------------------------
__global__ void whalf_kernel(const float* __restrict__ W1, const float* __restrict__ W2,
                             __half* __restrict__ w1h, __half* __restrict__ w2h) {
    int i = blockIdx.x * 256 + threadIdx.x;   // 16384
    w1h[i] = __float2half_rn(W1[i]);
    w2h[i] = __float2half_rn(W2[i]);
}

// ------------------------- 1) kNN: warp per query, register-resident ---------
__global__ __launch_bounds__(256)
void knn_kernel(const float* __restrict__ pts, int* __restrict__ idxout) {
    __shared__ float sx[NN], sy[NN], sz[NN], sxx[NN];
    int t = threadIdx.x;
    int wid = t >> 5, lane = t & 31;
    int blk = blockIdx.x;
    int b = blk >> 7;
    int n = ((blk & 127) << 3) + wid;
    const float* P = pts + (size_t)b * 3 * NN;
    for (int m = t; m < NN; m += 256) {
        float x = P[m], y = P[NN + m], z = P[2*NN + m];
        sx[m] = x; sy[m] = y; sz[m] = z;
        sxx[m] = x*x + y*y + z*z;
    }
    __syncthreads();
    float qx = sx[n], qy = sy[n], qz = sz[n], qxx = sxx[n];
    float d[32];
    #pragma unroll
    for (int j = 0; j < 32; j++) {
        int m = j*32 + lane;
        float dd = 2.f*(qx*sx[m] + qy*sy[m] + qz*sz[m]) - qxx - sxx[m];
        d[j] = (m == n) ? -INFINITY : dd;
    }
    int* op = idxout + ((size_t)b*NN + n) * KNN;
    unsigned alive = 0xffffffffu;
    for (int r = 0; r < KNN; r++) {
        float bv = -INFINITY; int bj = 0;
        #pragma unroll
        for (int j = 0; j < 32; j++) {
            float dj = (alive & (1u << j)) ? d[j] : -INFINITY;
            if (dj > bv) { bv = dj; bj = j; }
        }
        int bi = bj*32 + lane;
        #pragma unroll
        for (int s = 16; s > 0; s >>= 1) {
            float ov = __shfl_down_sync(0xffffffffu, bv, s);
            int   oi = __shfl_down_sync(0xffffffffu, bi, s);
            if (ov > bv || (ov == bv && oi < bi)) { bv = ov; bi = oi; }
        }
        bi = __shfl_sync(0xffffffffu, bi, 0);
        if (lane == 0) op[r] = bi;
        if ((bi & 31) == lane) alive &= ~(1u << (bi >> 5));
    }
}

// ------------------------- 2) per-point GEMVs --------------------------------
__global__ void feat_kernel(const float* __restrict__ f,
                            const float* __restrict__ W0,
                            const float* __restrict__ Wsc,
                            float* __restrict__ center,
                            float* __restrict__ h,
                            float* __restrict__ sc) {
    __shared__ float fs[CIN][16];
    int base = blockIdx.x * 16;
    int b = base >> 10, n0 = base & 1023;
    int t = threadIdx.x;
    #pragma unroll
    for (int i = 0; i < 8; i++) {
        int idx = t + 128*i;
        int c = idx >> 4, j = idx & 15;
        fs[c][j] = f[(size_t)b*CIN*NN + c*NN + n0 + j];
    }
    __syncthreads();
    int o = t;
    float ctr[16], hh[16], ss[16];
    #pragma unroll
    for (int j = 0; j < 16; j++) { ctr[j]=0.f; hh[j]=0.f; ss[j]=0.f; }
    for (int c = 0; c < CIN; c++) {
        float w0a = W0[o*128 + c];
        float w0b = W0[o*128 + 64 + c];
        float ws  = Wsc[o*64 + c];
        float wc  = w0a - w0b;
        const float* fr = fs[c];
        #pragma unroll
        for (int j = 0; j < 16; j++) {
            float fv = fr[j];
            ctr[j] = fmaf(wc,  fv, ctr[j]);
            hh[j]  = fmaf(w0b, fv, hh[j]);
            ss[j]  = fmaf(ws,  fv, ss[j]);
        }
    }
    #pragma unroll
    for (int j = 0; j < 16; j++) {
        int row = base + j;
        center[row*CO + o] = ctr[j];
        h[row*CO + o]      = hh[j];
        sc[row*CO + o]     = ss[j];
    }
}

// ------------------------- 3) layer-0 stats only -----------------------------
__global__ void buildstats_kernel(const float* __restrict__ center,
                                  const float* __restrict__ h,
                                  const int* __restrict__ idx,
                                  float* __restrict__ part) {
    __shared__ float red[8][132];
    int t = threadIdx.x;
    int oq = (t & 31) << 2;
    int strip = t >> 5;
    int bn = blockIdx.x * 8 + strip;
    int b = bn >> 10;
    float4 c4 = *reinterpret_cast<const float4*>(&center[bn*CO + oq]);
    const int* ip = idx + bn*KNN;
    float s0=0,s1=0,s2=0,s3=0, q0=0,q1=0,q2=0,q3=0;
    #pragma unroll
    for (int k = 0; k < KNN; k++) {
        int gi = ip[k];
        float4 h4 = *reinterpret_cast<const float4*>(&h[(b*NN + gi)*CO + oq]);
        float vx = c4.x + h4.x, vy = c4.y + h4.y, vz = c4.z + h4.z, vw = c4.w + h4.w;
        s0 += vx; s1 += vy; s2 += vz; s3 += vw;
        q0 = fmaf(vx,vx,q0); q1 = fmaf(vy,vy,q1); q2 = fmaf(vz,vz,q2); q3 = fmaf(vw,vw,q3);
    }
    red[strip][oq+0]=s0; red[strip][oq+1]=s1; red[strip][oq+2]=s2; red[strip][oq+3]=s3;
    __syncthreads();
    if (t < 128) {
        float s = 0;
        #pragma unroll
        for (int q = 0; q < 8; q++) s += red[q][t];
        part[blockIdx.x*256 + t] = s;
    }
    __syncthreads();
    red[strip][oq+0]=q0; red[strip][oq+1]=q1; red[strip][oq+2]=q2; red[strip][oq+3]=q3;
    __syncthreads();
    if (t < 128) {
        float s = 0;
        #pragma unroll
        for (int q = 0; q < 8; q++) s += red[q][t];
        part[blockIdx.x*256 + 128 + t] = s;
    }
}

// ------------------------- 4) stats: partials -> (a, d) ----------------------
__global__ void stats_kernel(const float* __restrict__ part, int nparts,
                             const float* __restrict__ g, const float* __restrict__ bt,
                             float* __restrict__ coef, float invM) {
    __shared__ float ss[256], qq[256];
    int o = blockIdx.x, t = threadIdx.x;
    float s = 0.f, q = 0.f;
    for (int p = t; p < nparts; p += 256) {
        s += part[p*256 + o];
        q += part[p*256 + 128 + o];
    }
    ss[t] = s; qq[t] = q;
    __syncthreads();
    for (int st = 128; st > 0; st >>= 1) {
        if (t < st) { ss[t] += ss[t+st]; qq[t] += qq[t+st]; }
        __syncthreads();
    }
    if (t == 0) {
        float mean = ss[0] * invM;
        float var  = qq[0] * invM - mean*mean;
        float a = g[o] / sqrtf(var + EPSV);
        coef[o] = a;
        coef[128 + o] = bt[o] - mean * a;
    }
}

// coalesced partial-sum over sc (rows x 128), 128 rows per block
__global__ void colpart_kernel(const float* __restrict__ X, float* __restrict__ part) {
    __shared__ float sm0[2][128], sm1[2][128];
    int t = threadIdx.x;
    int o = t & 127, hf = t >> 7;
    int r0 = blockIdx.x * 128 + hf * 64;
    float s = 0.f, q = 0.f;
    for (int i = 0; i < 64; i++) {
        float v = X[(size_t)(r0 + i)*CO + o];
        s += v; q = fmaf(v, v, q);
    }
    sm0[hf][o] = s; sm1[hf][o] = q;
    __syncthreads();
    if (t < 128) {
        part[blockIdx.x*256 + t]       = sm0[0][t] + sm0[1][t];
        part[blockIdx.x*256 + 128 + t] = sm1[0][t] + sm1[1][t];
    }
}

// ------------------------- pipelined mma.sync fp16 GEMM ----------------------
// 256 threads, tile 128m x 128n, K=128. W fp16 smem-resident; A single-pass fp16.
// A quarters (32 k) double-buffered: prefetch LDG -> mma -> cvt+STS.
__device__ __forceinline__ void a_prefetch(float4* rx, bool fused,
                                           const __half* __restrict__ X16,
                                           const float* __restrict__ h,
                                           const int* offH, size_t mbase, int cq, int t) {
    #pragma unroll
    for (int i = 0; i < 4; i++) {
        int e = t + 256*i;
        int c4 = e & 7, m = e >> 3;
        if (fused) {
            rx[i] = *reinterpret_cast<const float4*>(h + offH[m] + cq + c4*4);
        } else {
            uint2 hv = *reinterpret_cast<const uint2*>(X16 + (mbase + m)*CO + cq + c4*4);
            float2 f01 = __half22float2(*reinterpret_cast<const __half2*>(&hv.x));
            float2 f23 = __half22float2(*reinterpret_cast<const __half2*>(&hv.y));
            rx[i] = make_float4(f01.x, f01.y, f23.x, f23.y);
        }
    }
}

__device__ __forceinline__ void a_convert(const float4* rx, bool fused,
                                          const float* __restrict__ center, const int* offC,
                                          char* buf,
                                          const float* sa, const float* sd, int cq, int t) {
    #pragma unroll
    for (int i = 0; i < 4; i++) {
        int e = t + 256*i;
        int c4 = e & 7, m = e >> 3;
        int c0 = c4*4;
        float v0 = rx[i].x, v1 = rx[i].y, v2 = rx[i].z, v3 = rx[i].w;
        if (fused) {
            float4 cv = *reinterpret_cast<const float4*>(center + offC[m] + cq + c0);
            v0 += cv.x; v1 += cv.y; v2 += cv.z; v3 += cv.w;
        }
        v0 = fmaxf(fmaf(sa[cq+c0+0], v0, sd[cq+c0+0]), 0.f);
        v1 = fmaxf(fmaf(sa[cq+c0+1], v1, sd[cq+c0+1]), 0.f);
        v2 = fmaxf(fmaf(sa[cq+c0+2], v2, sd[cq+c0+2]), 0.f);
        v3 = fmaxf(fmaf(sa[cq+c0+3], v3, sd[cq+c0+3]), 0.f);
        __half h0 = __float2half_rn(v0), h1 = __float2half_rn(v1);
        __half h2 = __float2half_rn(v2), h3 = __float2half_rn(v3);
        *reinterpret_cast<uint2*>(buf + m*80 + c0*2) =
            make_uint2(packh2(h0, h1), packh2(h2, h3));
    }
}

__device__ __forceinline__ void gemm_mma_core(
    bool fused, const __half* __restrict__ X16,
    const float* __restrict__ center, const float* __restrict__ h,
    const int* __restrict__ idx,
    const __half* __restrict__ Wh,
    const float* __restrict__ coef,
    __half* __restrict__ Y, float* __restrict__ part)
{
    extern __shared__ char smem[];
    int t = threadIdx.x;
    int wid = t >> 5, lane = t & 31;
    int wm = wid >> 2, wn = wid & 3;       // warp grid 2m x 4n
    int m0w = wm * 64, n0w = wn * 32;
    int g = lane >> 2, q = lane & 3;
    size_t mbase = (size_t)blockIdx.x * 128;

    float* sa = (float*)(smem + DB_SA);
    float* sd = (float*)(smem + DB_SD);
    int* offC = (int*)(smem + DB_OFFC);
    int* offH = (int*)(smem + DB_OFFH);

    if (t < 128) {
        sa[t] = coef[t];
        sd[t] = coef[128 + t];
        if (fused) {
            int G = (int)mbase + t;
            int bn = G >> 4;
            int gi = idx[G];
            offC[t] = bn * CO;
            offH[t] = ((bn >> 10) * NN + gi) * CO;
        }
    }
    // load W into smem, rows stride 136 halves (68 u32)
    {
        const uint32_t* wh = reinterpret_cast<const uint32_t*>(Wh);
        uint32_t* bh = reinterpret_cast<uint32_t*>(smem + DB_BH);
        #pragma unroll
        for (int i = 0; i < 32; i++) {
            int e = t + 256*i;          // 8192 u32
            int c2 = e & 63, o = e >> 6;
            bh[o*68 + c2] = wh[e];
        }
    }
    __syncthreads();

    // build quarter 0 into buf 0
    {
        float4 rx[4];
        a_prefetch(rx, fused, X16, h, offH, mbase, 0, t);
        a_convert(rx, fused, center, offC, smem + DB_A, sa, sd, 0, t);
    }
    __syncthreads();

    uint32_t sb = smem_u32(smem);
    uint32_t aOffLane = (uint32_t)((m0w + (lane & 15)) * 80 + ((lane >> 4) << 4));
    uint32_t bRow = (uint32_t)(n0w + (lane & 7) + ((lane >> 4) << 3));
    uint32_t bHiBase = sb + DB_BH + bRow * 272 + (((lane >> 3) & 1) << 4);

    float acc[4][4][4];
    #pragma unroll
    for (int a = 0; a < 4; a++)
        #pragma unroll
        for (int b = 0; b < 4; b++)
            #pragma unroll
            for (int r = 0; r < 4; r++) acc[a][b][r] = 0.f;

    for (int kq = 0; kq < 4; kq++) {
        int p = kq & 1;
        float4 rx[4];
        if (kq < 3) a_prefetch(rx, fused, X16, h, offH, mbase, (kq+1)*32, t);

        uint32_t aHi = sb + DB_A + (uint32_t)(p*10240) + aOffLane;
        #pragma unroll
        for (int ks = 0; ks < 2; ks++) {
            uint32_t koffA = (uint32_t)(ks * 32);
            uint32_t koffB = (uint32_t)(kq * 64 + ks * 32);
            uint32_t bh0[4], bh1[4];
            ldsm4(bh0, bHiBase + koffB);
            ldsm4(bh1, bHiBase + 16*272 + koffB);
            #pragma unroll
            for (int a = 0; a < 4; a++) {
                uint32_t ahi[4];
                ldsm4(ahi, aHi + (uint32_t)(a*16*80) + koffA);
                mma_f16(acc[a][0], ahi, bh0[0], bh0[1]);
                mma_f16(acc[a][1], ahi, bh0[2], bh0[3]);
                mma_f16(acc[a][2], ahi, bh1[0], bh1[1]);
                mma_f16(acc[a][3], ahi, bh1[2], bh1[3]);
            }
        }
        if (kq < 3) {
            char* nb = smem + DB_A + (1 - p) * 10240;
            a_convert(rx, fused, center, offC, nb, sa, sd, (kq+1)*32, t);
        }
        __syncthreads();
    }

    // epilogue: store Y (fp16) + BN partials (fp32)
    float ls[4][2], lq[4][2];
    #pragma unroll
    for (int b = 0; b < 4; b++) { ls[b][0]=0.f; ls[b][1]=0.f; lq[b][0]=0.f; lq[b][1]=0.f; }
    #pragma unroll
    for (int a = 0; a < 4; a++) {
        #pragma unroll
        for (int hf = 0; hf < 2; hf++) {
            int row = m0w + 16*a + g + 8*hf;
            __half* yr = Y + (mbase + row)*CO + n0w + 2*q;
            #pragma unroll
            for (int b = 0; b < 4; b++) {
                float c0 = acc[a][b][2*hf], c1 = acc[a][b][2*hf + 1];
                *reinterpret_cast<uint32_t*>(yr + 8*b) =
                    packh2(__float2half_rn(c0), __float2half_rn(c1));
                ls[b][0] += c0; ls[b][1] += c1;
                lq[b][0] = fmaf(c0, c0, lq[b][0]);
                lq[b][1] = fmaf(c1, c1, lq[b][1]);
            }
        }
    }
    #pragma unroll
    for (int b = 0; b < 4; b++) {
        #pragma unroll
        for (int p2 = 0; p2 < 2; p2++) {
            #pragma unroll
            for (int off = 4; off < 32; off <<= 1) {
                ls[b][p2] += __shfl_xor_sync(0xffffffffu, ls[b][p2], off);
                lq[b][p2] += __shfl_xor_sync(0xffffffffu, lq[b][p2], off);
            }
        }
    }
    float* redS = (float*)(smem + DB_A);          // overlay (A bufs dead)
    float* redQ = (float*)(smem + DB_A + 4096);
    if (lane < 4) {
        #pragma unroll
        for (int b = 0; b < 4; b++) {
            #pragma unroll
            for (int p2 = 0; p2 < 2; p2++) {
                int cs = 8*b + 2*lane + p2;
                redS[wid*32 + cs] = ls[b][p2];
                redQ[wid*32 + cs] = lq[b][p2];
            }
        }
    }
    __syncthreads();
    if (t < 128) {
        int wnc = t >> 5, cw = t & 31;
        float Sv = redS[wnc*32 + cw] + redS[(wnc+4)*32 + cw];
        float Qv = redQ[wnc*32 + cw] + redQ[(wnc+4)*32 + cw];
        part[blockIdx.x*256 + t]       = Sv;
        part[blockIdx.x*256 + 128 + t] = Qv;
    }
}

__global__ __launch_bounds__(256, 2)
void gemm1_mma(const float* __restrict__ center, const float* __restrict__ h,
               const int* __restrict__ idx,
               const __half* __restrict__ Wh,
               const float* __restrict__ coef, __half* __restrict__ Y,
               float* __restrict__ part) {
    gemm_mma_core(true, nullptr, center, h, idx, Wh, coef, Y, part);
}

__global__ __launch_bounds__(256, 2)
void gemm2_mma(const __half* __restrict__ X16,
               const __half* __restrict__ Wh,
               const float* __restrict__ coef, __half* __restrict__ Y,
               float* __restrict__ part) {
    gemm_mma_core(false, X16, nullptr, nullptr, nullptr, Wh, coef, Y, part);
}

// ------------------------- final: mean_k relu(bn2) + bn_sc + relu, transpose -
// grid 4096 = 32 b x 128 groups of 8 n-rows; x2 is fp16
__global__ void final_kernel(const __half* __restrict__ x2, const float* __restrict__ sc,
                             const float* __restrict__ coef2, const float* __restrict__ coefsc,
                             float* __restrict__ out) {
    __shared__ float tile[8*129];
    int t = threadIdx.x;
    int blk = blockIdx.x;
    int b = blk >> 7;
    int n0 = (blk & 127) << 3;
    #pragma unroll
    for (int i = 0; i < 4; i++) {
        int idx = t + 256*i;
        int o = idx & 127, nn = idx >> 7;
        int bn = b*NN + n0 + nn;
        float a2 = coef2[o], d2 = coef2[128 + o];
        const __half* xr = x2 + (size_t)bn * KNN * CO + o;
        float s = 0.f;
        #pragma unroll
        for (int k = 0; k < KNN; k++)
            s += fmaxf(fmaf(a2, __half2float(xr[k*CO]), d2), 0.f);
        float scv = sc[bn*CO + o];
        float as = coefsc[o], ds = coefsc[128 + o];
        tile[nn*129 + o] = fmaxf(fmaf(as, scv, ds) + s * (1.f/16.f), 0.f);
    }
    __syncthreads();
    #pragma unroll
    for (int i = 0; i < 4; i++) {
        int idx = t + 256*i;
        int nn = idx & 7, o = idx >> 3;
        out[(size_t)b*CO*NN + o*NN + n0 + nn] = tile[nn*129 + o];
    }
}

// ------------------------- host launcher -------------------------------------
extern "C" void kernel_launch(void* const* d_in, const int* in_sizes, int n_in,
                              void* d_out, int out_size) {
    const float* points   = (const float*)d_in[0];
    const float* features = (const float*)d_in[1];
    const float* W0  = (const float*)d_in[2];
    const float* g0  = (const float*)d_in[3];
    const float* b0  = (const float*)d_in[4];
    const float* W1  = (const float*)d_in[5];
    const float* g1  = (const float*)d_in[6];
    const float* b1  = (const float*)d_in[7];
    const float* W2  = (const float*)d_in[8];
    const float* g2  = (const float*)d_in[9];
    const float* b2  = (const float*)d_in[10];
    const float* Wsc = (const float*)d_in[11];
    const float* gsc = (const float*)d_in[12];
    const float* bsc = (const float*)d_in[13];
    float* out = (float*)d_out;

    void *p_idx, *p_center, *p_h, *p_sc, *p_x1, *p_x2, *p_part, *p_partsc, *p_coef;
    void *p_w1h, *p_w2h;
    cudaGetSymbolAddress(&p_idx,    g_idx);
    cudaGetSymbolAddress(&p_center, g_center);
    cudaGetSymbolAddress(&p_h,      g_h);
    cudaGetSymbolAddress(&p_sc,     g_sc);
    cudaGetSymbolAddress(&p_x1,     g_x1);
    cudaGetSymbolAddress(&p_x2,     g_x2);
    cudaGetSymbolAddress(&p_part,   g_part);
    cudaGetSymbolAddress(&p_partsc, g_partsc);
    cudaGetSymbolAddress(&p_coef,   g_coef);
    cudaGetSymbolAddress(&p_w1h,    g_w1h);
    cudaGetSymbolAddress(&p_w2h,    g_w2h);

    int*    idx    = (int*)p_idx;
    float*  center = (float*)p_center;
    float*  h      = (float*)p_h;
    float*  sc     = (float*)p_sc;
    __half* x1     = (__half*)p_x1;
    __half* x2     = (__half*)p_x2;
    float*  part   = (float*)p_part;
    float*  partsc = (float*)p_partsc;
    float*  coef0  = (float*)p_coef;
    float*  coef1  = coef0 + 256;
    float*  coef2  = coef0 + 512;
    float*  coef3  = coef0 + 768;
    __half* w1h = (__half*)p_w1h;
    __half* w2h = (__half*)p_w2h;

    const float invM  = 1.f / (float)ROWS;
    const float invMs = 1.f / (float)BNROWS;

    cudaFuncSetAttribute(gemm1_mma, cudaFuncAttributeMaxDynamicSharedMemorySize, DB_TOTAL);
    cudaFuncSetAttribute(gemm2_mma, cudaFuncAttributeMaxDynamicSharedMemorySize, DB_TOTAL);

    whalf_kernel<<<64, 256>>>(W1, W2, w1h, w2h);
    knn_kernel<<<GEMM_BLOCKS, 256>>>(points, idx);
    feat_kernel<<<BNROWS/16, 128>>>(features, W0, Wsc, center, h, sc);
    buildstats_kernel<<<GEMM_BLOCKS, 256>>>(center, h, idx, part);
    colpart_kernel<<<256, 256>>>(sc, partsc);
    stats_kernel<<<128, 256>>>(part, GEMM_BLOCKS, g0, b0, coef0, invM);
    stats_kernel<<<128, 256>>>(partsc, 256, gsc, bsc, coef3, invMs);
    gemm1_mma<<<GEMM_BLOCKS, 256, DB_TOTAL>>>(center, h, idx, w1h, coef0, x1, part);
    stats_kernel<<<128, 256>>>(part, GEMM_BLOCKS, g1, b1, coef1, invM);
    gemm2_mma<<<GEMM_BLOCKS, 256, DB_TOTAL>>>(x1, w2h, coef1, x2, part);
    stats_kernel<<<128, 256>>>(part, GEMM_BLOCKS, g2, b2, coef2, invM);
    final_kernel<<<4096, 256>>>(x2, sc, coef2, coef3, out);
}

// round 12
// speedup vs baseline: 5.2284x; 1.0868x over previous
#include <cuda_runtime.h>
#include <cuda_bf16.h>
#include <cuda_fp16.h>
#include <math.h>
#include <stdint.h>

// Problem constants
#define BB   32
#define NN   1024
#define CIN  64
#define CO   128
#define KNN  16
#define BNROWS (BB*NN)          // 32768
#define ROWS   (BNROWS*KNN)     // 524288
#define GEMM_BLOCKS (ROWS/128)  // 4096
#define EPSV 1e-5f

// ------------------------- device scratch (static, no allocs) ----------------
static __device__ int    g_idx[ROWS];                 // 2 MB
static __device__ float  g_center[BNROWS*CO];         // 16 MB
static __device__ float  g_h[BNROWS*CO];              // 16 MB
static __device__ float  g_sc[BNROWS*CO];             // 16 MB
static __device__ __half g_x1[(size_t)ROWS*CO];       // 134 MB (layer-1 out, fp16)
static __device__ __half g_x2[(size_t)ROWS*CO];       // 134 MB (layer-2 out, fp16)
static __device__ float  g_part[GEMM_BLOCKS*256];     // 4 MB
static __device__ float  g_partsc[256*256];           // 256 KB
static __device__ float  g_coef[4*256];               // (a[128],d[128]) x4
static __device__ __half g_w1h[CO*CO];                // fp16-rounded weights
static __device__ __half g_w2h[CO*CO];

// ------------------------- PTX helpers ---------------------------------------
__device__ __forceinline__ uint32_t smem_u32(const void* p) {
    uint32_t a;
    asm("{ .reg .u64 t; cvta.to.shared.u64 t, %1; cvt.u32.u64 %0, t; }" : "=r"(a) : "l"(p));
    return a;
}
__device__ __forceinline__ void ldsm4(uint32_t* r, uint32_t addr) {
    asm volatile("ldmatrix.sync.aligned.m8n8.x4.shared.b16 {%0,%1,%2,%3}, [%4];"
        : "=r"(r[0]), "=r"(r[1]), "=r"(r[2]), "=r"(r[3]) : "r"(addr));
}
__device__ __forceinline__ void mma_f16(float* c, const uint32_t* a, uint32_t b0, uint32_t b1) {
    asm volatile("mma.sync.aligned.m16n8k16.row.col.f32.f16.f16.f32 "
        "{%0,%1,%2,%3}, {%4,%5,%6,%7}, {%8,%9}, {%0,%1,%2,%3};"
        : "+f"(c[0]), "+f"(c[1]), "+f"(c[2]), "+f"(c[3])
        : "r"(a[0]), "r"(a[1]), "r"(a[2]), "r"(a[3]), "r"(b0), "r"(b1));
}
__device__ __forceinline__ uint32_t packh2(__half a, __half b) {
    return (uint32_t)__half_as_ushort(a) | ((uint32_t)__half_as_ushort(b) << 16);
}
__device__ __forceinline__ void cp_async16(uint32_t s, const void* g) {
    asm volatile("cp.async.cg.shared.global [%0], [%1], 16;" :: "r"(s), "l"(g) : "memory");
}
__device__ __forceinline__ void cp_commit() {
    asm volatile("cp.async.commit_group;" ::: "memory");
}
template<int N> __device__ __forceinline__ void cp_wait() {
    asm volatile("cp.async.wait_group %0;" :: "n"(N) : "memory");
}

// ------------------------- dynamic smem layout (bytes) ------------------------
// B (full K, resident): rows stride 136 halves = 272 B -> ldmatrix conflict-free
#define DB_BH    0          // 34816
#define DB_A     34816      // 2 x 10240 (A fp16, row stride 80 B) -> 55296
#define DB_RAW   55296      // 2 x 16384 raw staging (cp.async) -> 88064
#define DB_CTR   88064      // 4096 (center tile: 8 bn x 128 f32, gemm1 only)
#define DB_SA    92160      // 512
#define DB_SD    92672      // 512
#define DB_OFFH  93184      // 512
#define DB_TOTAL 93696

// ------------------------- 0) W fp16 precompute -------------------------------
__global__ void whalf_kernel(const float* __restrict__ W1, const float* __restrict__ W2,
                             __half* __restrict__ w1h, __half* __restrict__ w2h) {
    int i = blockIdx.x * 256 + threadIdx.x;   // 16384
    w1h[i] = __float2half_rn(W1[i]);
    w2h[i] = __float2half_rn(W2[i]);
}

// ------------------------- 1) kNN: warp per query, register-resident ---------
__global__ __launch_bounds__(256)
void knn_kernel(const float* __restrict__ pts, int* __restrict__ idxout) {
    __shared__ float sx[NN], sy[NN], sz[NN], sxx[NN];
    int t = threadIdx.x;
    int wid = t >> 5, lane = t & 31;
    int blk = blockIdx.x;
    int b = blk >> 7;
    int n = ((blk & 127) << 3) + wid;
    const float* P = pts + (size_t)b * 3 * NN;
    for (int m = t; m < NN; m += 256) {
        float x = P[m], y = P[NN + m], z = P[2*NN + m];
        sx[m] = x; sy[m] = y; sz[m] = z;
        sxx[m] = x*x + y*y + z*z;
    }
    __syncthreads();
    float qx = sx[n], qy = sy[n], qz = sz[n], qxx = sxx[n];
    float d[32];
    #pragma unroll
    for (int j = 0; j < 32; j++) {
        int m = j*32 + lane;
        float dd = 2.f*(qx*sx[m] + qy*sy[m] + qz*sz[m]) - qxx - sxx[m];
        d[j] = (m == n) ? -INFINITY : dd;
    }
    int* op = idxout + ((size_t)b*NN + n) * KNN;
    unsigned alive = 0xffffffffu;
    for (int r = 0; r < KNN; r++) {
        float bv = -INFINITY; int bj = 0;
        #pragma unroll
        for (int j = 0; j < 32; j++) {
            float dj = (alive & (1u << j)) ? d[j] : -INFINITY;
            if (dj > bv) { bv = dj; bj = j; }
        }
        int bi = bj*32 + lane;
        #pragma unroll
        for (int s = 16; s > 0; s >>= 1) {
            float ov = __shfl_down_sync(0xffffffffu, bv, s);
            int   oi = __shfl_down_sync(0xffffffffu, bi, s);
            if (ov > bv || (ov == bv && oi < bi)) { bv = ov; bi = oi; }
        }
        bi = __shfl_sync(0xffffffffu, bi, 0);
        if (lane == 0) op[r] = bi;
        if ((bi & 31) == lane) alive &= ~(1u << (bi >> 5));
    }
}

// ------------------------- 2) per-point GEMVs --------------------------------
__global__ void feat_kernel(const float* __restrict__ f,
                            const float* __restrict__ W0,
                            const float* __restrict__ Wsc,
                            float* __restrict__ center,
                            float* __restrict__ h,
                            float* __restrict__ sc) {
    __shared__ float fs[CIN][16];
    int base = blockIdx.x * 16;
    int b = base >> 10, n0 = base & 1023;
    int t = threadIdx.x;
    #pragma unroll
    for (int i = 0; i < 8; i++) {
        int idx = t + 128*i;
        int c = idx >> 4, j = idx & 15;
        fs[c][j] = f[(size_t)b*CIN*NN + c*NN + n0 + j];
    }
    __syncthreads();
    int o = t;
    float ctr[16], hh[16], ss[16];
    #pragma unroll
    for (int j = 0; j < 16; j++) { ctr[j]=0.f; hh[j]=0.f; ss[j]=0.f; }
    for (int c = 0; c < CIN; c++) {
        float w0a = W0[o*128 + c];
        float w0b = W0[o*128 + 64 + c];
        float ws  = Wsc[o*64 + c];
        float wc  = w0a - w0b;
        const float* fr = fs[c];
        #pragma unroll
        for (int j = 0; j < 16; j++) {
            float fv = fr[j];
            ctr[j] = fmaf(wc,  fv, ctr[j]);
            hh[j]  = fmaf(w0b, fv, hh[j]);
            ss[j]  = fmaf(ws,  fv, ss[j]);
        }
    }
    #pragma unroll
    for (int j = 0; j < 16; j++) {
        int row = base + j;
        center[row*CO + o] = ctr[j];
        h[row*CO + o]      = hh[j];
        sc[row*CO + o]     = ss[j];
    }
}

// ------------------------- 3) layer-0 stats only -----------------------------
__global__ void buildstats_kernel(const float* __restrict__ center,
                                  const float* __restrict__ h,
                                  const int* __restrict__ idx,
                                  float* __restrict__ part) {
    __shared__ float red[8][132];
    int t = threadIdx.x;
    int oq = (t & 31) << 2;
    int strip = t >> 5;
    int bn = blockIdx.x * 8 + strip;
    int b = bn >> 10;
    float4 c4 = *reinterpret_cast<const float4*>(&center[bn*CO + oq]);
    const int* ip = idx + bn*KNN;
    float s0=0,s1=0,s2=0,s3=0, q0=0,q1=0,q2=0,q3=0;
    #pragma unroll
    for (int k = 0; k < KNN; k++) {
        int gi = ip[k];
        float4 h4 = *reinterpret_cast<const float4*>(&h[(b*NN + gi)*CO + oq]);
        float vx = c4.x + h4.x, vy = c4.y + h4.y, vz = c4.z + h4.z, vw = c4.w + h4.w;
        s0 += vx; s1 += vy; s2 += vz; s3 += vw;
        q0 = fmaf(vx,vx,q0); q1 = fmaf(vy,vy,q1); q2 = fmaf(vz,vz,q2); q3 = fmaf(vw,vw,q3);
    }
    red[strip][oq+0]=s0; red[strip][oq+1]=s1; red[strip][oq+2]=s2; red[strip][oq+3]=s3;
    __syncthreads();
    if (t < 128) {
        float s = 0;
        #pragma unroll
        for (int q = 0; q < 8; q++) s += red[q][t];
        part[blockIdx.x*256 + t] = s;
    }
    __syncthreads();
    red[strip][oq+0]=q0; red[strip][oq+1]=q1; red[strip][oq+2]=q2; red[strip][oq+3]=q3;
    __syncthreads();
    if (t < 128) {
        float s = 0;
        #pragma unroll
        for (int q = 0; q < 8; q++) s += red[q][t];
        part[blockIdx.x*256 + 128 + t] = s;
    }
}

// ------------------------- 4) stats: partials -> (a, d) ----------------------
__global__ void stats_kernel(const float* __restrict__ part, int nparts,
                             const float* __restrict__ g, const float* __restrict__ bt,
                             float* __restrict__ coef, float invM) {
    __shared__ float ss[256], qq[256];
    int o = blockIdx.x, t = threadIdx.x;
    float s = 0.f, q = 0.f;
    for (int p = t; p < nparts; p += 256) {
        s += part[p*256 + o];
        q += part[p*256 + 128 + o];
    }
    ss[t] = s; qq[t] = q;
    __syncthreads();
    for (int st = 128; st > 0; st >>= 1) {
        if (t < st) { ss[t] += ss[t+st]; qq[t] += qq[t+st]; }
        __syncthreads();
    }
    if (t == 0) {
        float mean = ss[0] * invM;
        float var  = qq[0] * invM - mean*mean;
        float a = g[o] / sqrtf(var + EPSV);
        coef[o] = a;
        coef[128 + o] = bt[o] - mean * a;
    }
}

// coalesced partial-sum over sc (rows x 128), 128 rows per block
__global__ void colpart_kernel(const float* __restrict__ X, float* __restrict__ part) {
    __shared__ float sm0[2][128], sm1[2][128];
    int t = threadIdx.x;
    int o = t & 127, hf = t >> 7;
    int r0 = blockIdx.x * 128 + hf * 64;
    float s = 0.f, q = 0.f;
    for (int i = 0; i < 64; i++) {
        float v = X[(size_t)(r0 + i)*CO + o];
        s += v; q = fmaf(v, v, q);
    }
    sm0[hf][o] = s; sm1[hf][o] = q;
    __syncthreads();
    if (t < 128) {
        part[blockIdx.x*256 + t]       = sm0[0][t] + sm0[1][t];
        part[blockIdx.x*256 + 128 + t] = sm1[0][t] + sm1[1][t];
    }
}

// ------------------------- cp.async-pipelined fp16 GEMM ----------------------
// 256 threads, tile 128m x 128n, K=128 in 4 quarters of 32.
// Raw A quarters staged GMEM->SMEM via cp.async (depth 2); convert reads smem.
// gemm1 additionally keeps the center tile (8 bn x 128 ch) smem-resident.

__device__ __forceinline__ void issue_raw(bool fused, char* smem, uint32_t sb,
                                          const __half* __restrict__ X16,
                                          const float* __restrict__ h,
                                          const int* offH, size_t mbase,
                                          int cq, int buf, int t) {
    uint32_t dst0 = sb + DB_RAW + (uint32_t)(buf * 16384);
    if (fused) {
        // 128 rows x 128 B (fp32), 16B chunks: 1024 chunks / 256 thr = 4 each
        #pragma unroll
        for (int i = 0; i < 4; i++) {
            int chunk = t + 256*i;
            int row = chunk >> 3, c16 = chunk & 7;
            const float* src = h + offH[row] + cq + c16*4;
            cp_async16(dst0 + (uint32_t)(row*128 + c16*16), src);
        }
    } else {
        // 128 rows x 64 B (fp16), 16B chunks: 512 chunks / 256 thr = 2 each
        #pragma unroll
        for (int i = 0; i < 2; i++) {
            int chunk = t + 256*i;
            int row = chunk >> 2, c16 = chunk & 3;
            const __half* src = X16 + (mbase + row)*CO + cq + c16*8;
            cp_async16(dst0 + (uint32_t)(row*64 + c16*16), src);
        }
    }
}

__device__ __forceinline__ void convert_raw(bool fused, char* smem,
                                            const float* sa, const float* sd,
                                            int cq, int buf, char* abuf, int t) {
    const char* raw = smem + DB_RAW + buf * 16384;
    const float* ctr = (const float*)(smem + DB_CTR);
    #pragma unroll
    for (int i = 0; i < 4; i++) {
        int e = t + 256*i;
        int c4 = e & 7, m = e >> 3;
        int c0 = c4*4;
        float v0, v1, v2, v3;
        if (fused) {
            float4 hv = *reinterpret_cast<const float4*>(raw + m*128 + c0*4);
            float4 cv = *reinterpret_cast<const float4*>(ctr + (m >> 4)*CO + cq + c0);
            v0 = hv.x + cv.x; v1 = hv.y + cv.y; v2 = hv.z + cv.z; v3 = hv.w + cv.w;
        } else {
            uint2 hv = *reinterpret_cast<const uint2*>(raw + m*64 + c0*2);
            float2 f01 = __half22float2(*reinterpret_cast<const __half2*>(&hv.x));
            float2 f23 = __half22float2(*reinterpret_cast<const __half2*>(&hv.y));
            v0 = f01.x; v1 = f01.y; v2 = f23.x; v3 = f23.y;
        }
        v0 = fmaxf(fmaf(sa[cq+c0+0], v0, sd[cq+c0+0]), 0.f);
        v1 = fmaxf(fmaf(sa[cq+c0+1], v1, sd[cq+c0+1]), 0.f);
        v2 = fmaxf(fmaf(sa[cq+c0+2], v2, sd[cq+c0+2]), 0.f);
        v3 = fmaxf(fmaf(sa[cq+c0+3], v3, sd[cq+c0+3]), 0.f);
        __half h0 = __float2half_rn(v0), h1 = __float2half_rn(v1);
        __half h2 = __float2half_rn(v2), h3 = __float2half_rn(v3);
        *reinterpret_cast<uint2*>(abuf + m*80 + c0*2) =
            make_uint2(packh2(h0, h1), packh2(h2, h3));
    }
}

__device__ __forceinline__ void gemm_mma_core(
    bool fused, const __half* __restrict__ X16,
    const float* __restrict__ center, const float* __restrict__ h,
    const int* __restrict__ idx,
    const __half* __restrict__ Wh,
    const float* __restrict__ coef,
    __half* __restrict__ Y, float* __restrict__ part)
{
    extern __shared__ char smem[];
    int t = threadIdx.x;
    int wid = t >> 5, lane = t & 31;
    int wm = wid >> 2, wn = wid & 3;       // warp grid 2m x 4n
    int m0w = wm * 64, n0w = wn * 32;
    int g = lane >> 2, q = lane & 3;
    size_t mbase = (size_t)blockIdx.x * 128;

    float* sa = (float*)(smem + DB_SA);
    float* sd = (float*)(smem + DB_SD);
    int* offH = (int*)(smem + DB_OFFH);

    if (t < 128) {
        sa[t] = coef[t];
        sd[t] = coef[128 + t];
        if (fused) {
            int G = (int)mbase + t;
            int bn = G >> 4;
            int gi = idx[G];
            offH[t] = ((bn >> 10) * NN + gi) * CO;
        }
    }
    // load W into smem, rows stride 136 halves (68 u32)
    {
        const uint32_t* wh = reinterpret_cast<const uint32_t*>(Wh);
        uint32_t* bh = reinterpret_cast<uint32_t*>(smem + DB_BH);
        #pragma unroll
        for (int i = 0; i < 32; i++) {
            int e = t + 256*i;          // 8192 u32
            int c2 = e & 63, o = e >> 6;
            bh[o*68 + c2] = wh[e];
        }
    }
    // load center tile (8 bn x 128 ch) once (gemm1 only)
    if (fused) {
        float* ctr = (float*)(smem + DB_CTR);
        int bn0 = blockIdx.x * 8;
        #pragma unroll
        for (int i = 0; i < 4; i++) {
            int e = t + 256*i;          // 1024 floats
            ctr[e] = center[bn0*CO + e];
        }
    }
    __syncthreads();

    uint32_t sb = smem_u32(smem);

    // prologue: stage raw quarters 0 and 1, convert quarter 0
    issue_raw(fused, smem, sb, X16, h, offH, mbase, 0, 0, t);  cp_commit();
    issue_raw(fused, smem, sb, X16, h, offH, mbase, 32, 1, t); cp_commit();
    cp_wait<1>();
    __syncthreads();
    convert_raw(fused, smem, sa, sd, 0, 0, smem + DB_A, t);
    __syncthreads();

    uint32_t aOffLane = (uint32_t)((m0w + (lane & 15)) * 80 + ((lane >> 4) << 4));
    uint32_t bRow = (uint32_t)(n0w + (lane & 7) + ((lane >> 4) << 3));
    uint32_t bHiBase = sb + DB_BH + bRow * 272 + (((lane >> 3) & 1) << 4);

    float acc[4][4][4];
    #pragma unroll
    for (int a = 0; a < 4; a++)
        #pragma unroll
        for (int b = 0; b < 4; b++)
            #pragma unroll
            for (int r = 0; r < 4; r++) acc[a][b][r] = 0.f;

    #pragma unroll
    for (int kq = 0; kq < 4; kq++) {
        int p = kq & 1;
        uint32_t aHi = sb + DB_A + (uint32_t)(p*10240) + aOffLane;
        #pragma unroll
        for (int ks = 0; ks < 2; ks++) {
            uint32_t koffA = (uint32_t)(ks * 32);
            uint32_t koffB = (uint32_t)(kq * 64 + ks * 32);
            uint32_t bh0[4], bh1[4];
            ldsm4(bh0, bHiBase + koffB);
            ldsm4(bh1, bHiBase + 16*272 + koffB);
            #pragma unroll
            for (int a = 0; a < 4; a++) {
                uint32_t ahi[4];
                ldsm4(ahi, aHi + (uint32_t)(a*16*80) + koffA);
                mma_f16(acc[a][0], ahi, bh0[0], bh0[1]);
                mma_f16(acc[a][1], ahi, bh0[2], bh0[3]);
                mma_f16(acc[a][2], ahi, bh1[0], bh1[1]);
                mma_f16(acc[a][3], ahi, bh1[2], bh1[3]);
            }
        }
        if (kq < 2) {
            issue_raw(fused, smem, sb, X16, h, offH, mbase, (kq+2)*32, kq & 1, t);
            cp_commit();
        }
        if (kq < 3) {
            if (kq < 2) cp_wait<1>(); else cp_wait<0>();
            __syncthreads();   // raw[kq+1] visible; all warps done with A buf (1-p)
            convert_raw(fused, smem, sa, sd, (kq+1)*32, (kq+1) & 1,
                        smem + DB_A + (1 - p) * 10240, t);
        }
        __syncthreads();
    }

    // epilogue: store Y (fp16) + BN partials (fp32)
    float ls[4][2], lq[4][2];
    #pragma unroll
    for (int b = 0; b < 4; b++) { ls[b][0]=0.f; ls[b][1]=0.f; lq[b][0]=0.f; lq[b][1]=0.f; }
    #pragma unroll
    for (int a = 0; a < 4; a++) {
        #pragma unroll
        for (int hf = 0; hf < 2; hf++) {
            int row = m0w + 16*a + g + 8*hf;
            __half* yr = Y + (mbase + row)*CO + n0w + 2*q;
            #pragma unroll
            for (int b = 0; b < 4; b++) {
                float c0 = acc[a][b][2*hf], c1 = acc[a][b][2*hf + 1];
                *reinterpret_cast<uint32_t*>(yr + 8*b) =
                    packh2(__float2half_rn(c0), __float2half_rn(c1));
                ls[b][0] += c0; ls[b][1] += c1;
                lq[b][0] = fmaf(c0, c0, lq[b][0]);
                lq[b][1] = fmaf(c1, c1, lq[b][1]);
            }
        }
    }
    #pragma unroll
    for (int b = 0; b < 4; b++) {
        #pragma unroll
        for (int p2 = 0; p2 < 2; p2++) {
            #pragma unroll
            for (int off = 4; off < 32; off <<= 1) {
                ls[b][p2] += __shfl_xor_sync(0xffffffffu, ls[b][p2], off);
                lq[b][p2] += __shfl_xor_sync(0xffffffffu, lq[b][p2], off);
            }
        }
    }
    float* redS = (float*)(smem + DB_A);          // overlay (A bufs dead)
    float* redQ = (float*)(smem + DB_A + 4096);
    if (lane < 4) {
        #pragma unroll
        for (int b = 0; b < 4; b++) {
            #pragma unroll
            for (int p2 = 0; p2 < 2; p2++) {
                int cs = 8*b + 2*lane + p2;
                redS[wid*32 + cs] = ls[b][p2];
                redQ[wid*32 + cs] = lq[b][p2];
            }
        }
    }
    __syncthreads();
    if (t < 128) {
        int wnc = t >> 5, cw = t & 31;
        float Sv = redS[wnc*32 + cw] + redS[(wnc+4)*32 + cw];
        float Qv = redQ[wnc*32 + cw] + redQ[(wnc+4)*32 + cw];
        part[blockIdx.x*256 + t]       = Sv;
        part[blockIdx.x*256 + 128 + t] = Qv;
    }
}

__global__ __launch_bounds__(256, 2)
void gemm1_mma(const float* __restrict__ center, const float* __restrict__ h,
               const int* __restrict__ idx,
               const __half* __restrict__ Wh,
               const float* __restrict__ coef, __half* __restrict__ Y,
               float* __restrict__ part) {
    gemm_mma_core(true, nullptr, center, h, idx, Wh, coef, Y, part);
}

__global__ __launch_bounds__(256, 2)
void gemm2_mma(const __half* __restrict__ X16,
               const __half* __restrict__ Wh,
               const float* __restrict__ coef, __half* __restrict__ Y,
               float* __restrict__ part) {
    gemm_mma_core(false, X16, nullptr, nullptr, nullptr, Wh, coef, Y, part);
}

// ------------------------- final: mean_k relu(bn2) + bn_sc + relu, transpose -
// grid 4096 = 32 b x 128 groups of 8 n-rows; x2 is fp16
__global__ void final_kernel(const __half* __restrict__ x2, const float* __restrict__ sc,
                             const float* __restrict__ coef2, const float* __restrict__ coefsc,
                             float* __restrict__ out) {
    __shared__ float tile[8*129];
    int t = threadIdx.x;
    int blk = blockIdx.x;
    int b = blk >> 7;
    int n0 = (blk & 127) << 3;
    #pragma unroll
    for (int i = 0; i < 4; i++) {
        int idx = t + 256*i;
        int o = idx & 127, nn = idx >> 7;
        int bn = b*NN + n0 + nn;
        float a2 = coef2[o], d2 = coef2[128 + o];
        const __half* xr = x2 + (size_t)bn * KNN * CO + o;
        float s = 0.f;
        #pragma unroll
        for (int k = 0; k < KNN; k++)
            s += fmaxf(fmaf(a2, __half2float(xr[k*CO]), d2), 0.f);
        float scv = sc[bn*CO + o];
        float as = coefsc[o], ds = coefsc[128 + o];
        tile[nn*129 + o] = fmaxf(fmaf(as, scv, ds) + s * (1.f/16.f), 0.f);
    }
    __syncthreads();
    #pragma unroll
    for (int i = 0; i < 4; i++) {
        int idx = t + 256*i;
        int nn = idx & 7, o = idx >> 3;
        out[(size_t)b*CO*NN + o*NN + n0 + nn] = tile[nn*129 + o];
    }
}

// ------------------------- host launcher -------------------------------------
extern "C" void kernel_launch(void* const* d_in, const int* in_sizes, int n_in,
                              void* d_out, int out_size) {
    const float* points   = (const float*)d_in[0];
    const float* features = (const float*)d_in[1];
    const float* W0  = (const float*)d_in[2];
    const float* g0  = (const float*)d_in[3];
    const float* b0  = (const float*)d_in[4];
    const float* W1  = (const float*)d_in[5];
    const float* g1  = (const float*)d_in[6];
    const float* b1  = (const float*)d_in[7];
    const float* W2  = (const float*)d_in[8];
    const float* g2  = (const float*)d_in[9];
    const float* b2  = (const float*)d_in[10];
    const float* Wsc = (const float*)d_in[11];
    const float* gsc = (const float*)d_in[12];
    const float* bsc = (const float*)d_in[13];
    float* out = (float*)d_out;

    void *p_idx, *p_center, *p_h, *p_sc, *p_x1, *p_x2, *p_part, *p_partsc, *p_coef;
    void *p_w1h, *p_w2h;
    cudaGetSymbolAddress(&p_idx,    g_idx);
    cudaGetSymbolAddress(&p_center, g_center);
    cudaGetSymbolAddress(&p_h,      g_h);
    cudaGetSymbolAddress(&p_sc,     g_sc);
    cudaGetSymbolAddress(&p_x1,     g_x1);
    cudaGetSymbolAddress(&p_x2,     g_x2);
    cudaGetSymbolAddress(&p_part,   g_part);
    cudaGetSymbolAddress(&p_partsc, g_partsc);
    cudaGetSymbolAddress(&p_coef,   g_coef);
    cudaGetSymbolAddress(&p_w1h,    g_w1h);
    cudaGetSymbolAddress(&p_w2h,    g_w2h);

    int*    idx    = (int*)p_idx;
    float*  center = (float*)p_center;
    float*  h      = (float*)p_h;
    float*  sc     = (float*)p_sc;
    __half* x1     = (__half*)p_x1;
    __half* x2     = (__half*)p_x2;
    float*  part   = (float*)p_part;
    float*  partsc = (float*)p_partsc;
    float*  coef0  = (float*)p_coef;
    float*  coef1  = coef0 + 256;
    float*  coef2  = coef0 + 512;
    float*  coef3  = coef0 + 768;
    __half* w1h = (__half*)p_w1h;
    __half* w2h = (__half*)p_w2h;

    const float invM  = 1.f / (float)ROWS;
    const float invMs = 1.f / (float)BNROWS;

    cudaFuncSetAttribute(gemm1_mma, cudaFuncAttributeMaxDynamicSharedMemorySize, DB_TOTAL);
    cudaFuncSetAttribute(gemm2_mma, cudaFuncAttributeMaxDynamicSharedMemorySize, DB_TOTAL);

    whalf_kernel<<<64, 256>>>(W1, W2, w1h, w2h);
    knn_kernel<<<GEMM_BLOCKS, 256>>>(points, idx);
    feat_kernel<<<BNROWS/16, 128>>>(features, W0, Wsc, center, h, sc);
    buildstats_kernel<<<GEMM_BLOCKS, 256>>>(center, h, idx, part);
    colpart_kernel<<<256, 256>>>(sc, partsc);
    stats_kernel<<<128, 256>>>(part, GEMM_BLOCKS, g0, b0, coef0, invM);
    stats_kernel<<<128, 256>>>(partsc, 256, gsc, bsc, coef3, invMs);
    gemm1_mma<<<GEMM_BLOCKS, 256, DB_TOTAL>>>(center, h, idx, w1h, coef0, x1, part);
    stats_kernel<<<128, 256>>>(part, GEMM_BLOCKS, g1, b1, coef1, invM);
    gemm2_mma<<<GEMM_BLOCKS, 256, DB_TOTAL>>>(x1, w2h, coef1, x2, part);
    stats_kernel<<<128, 256>>>(part, GEMM_BLOCKS, g2, b2, coef2, invM);
    final_kernel<<<4096, 256>>>(x2, sc, coef2, coef3, out);
}